// round 2
// baseline (speedup 1.0000x reference)
#include <cuda_runtime.h>
#include <cuda_bf16.h>
#include <cstdint>

typedef __nv_bfloat16 bf16;

#define NB   4
#define SEQ  2048
#define DM   1024
#define MTOT (NB*SEQ)          // 8192

#define BM 128
#define BN 128
#define BK 32
#define STAGES 3
#define TILE_BYTES (BM*BK*2)               // 8192 B per operand tile
#define SMEM_BYTES (STAGES*4*TILE_BYTES)   // 98304 B

// ------------------------- scratch (__device__ globals; no allocs) ----------
__device__ bf16  g_Xh[MTOT*DM],  g_Xl[MTOT*DM];
__device__ bf16  g_Wqh[DM*DM],   g_Wql[DM*DM];
__device__ bf16  g_Wkh[DM*DM],   g_Wkl[DM*DM];
__device__ bf16  g_Wvh[DM*DM],   g_Wvl[DM*DM];
__device__ bf16  g_Qh[MTOT*DM],  g_Ql[MTOT*DM];
__device__ bf16  g_Kh[MTOT*DM],  g_Kl[MTOT*DM];
__device__ bf16  g_Vth[DM*MTOT], g_Vtl[DM*MTOT];
__device__ float g_S[MTOT*SEQ];
__device__ bf16  g_Ph[MTOT*SEQ], g_Pl[MTOT*SEQ];

// ------------------------- PTX helpers -------------------------------------
__device__ __forceinline__ void cp16(void* s, const void* g) {
    uint32_t sa = (uint32_t)__cvta_generic_to_shared(s);
    asm volatile("cp.async.cg.shared.global [%0], [%1], 16;\n" :: "r"(sa), "l"(g));
}
__device__ __forceinline__ void ldsm4(uint32_t* r, const void* p) {
    uint32_t a = (uint32_t)__cvta_generic_to_shared(p);
    asm volatile("ldmatrix.sync.aligned.m8n8.x4.shared.b16 {%0,%1,%2,%3}, [%4];\n"
                 : "=r"(r[0]), "=r"(r[1]), "=r"(r[2]), "=r"(r[3]) : "r"(a));
}
__device__ __forceinline__ void mma_bf16(float* c, const uint32_t* a, const uint32_t* b) {
    asm volatile("mma.sync.aligned.m16n8k16.row.col.f32.bf16.bf16.f32 "
                 "{%0,%1,%2,%3}, {%4,%5,%6,%7}, {%8,%9}, {%0,%1,%2,%3};\n"
                 : "+f"(c[0]), "+f"(c[1]), "+f"(c[2]), "+f"(c[3])
                 : "r"(a[0]), "r"(a[1]), "r"(a[2]), "r"(a[3]), "r"(b[0]), "r"(b[1]));
}
// 16B-chunk XOR swizzle: row stride 64B, chunk' = chunk ^ ((row>>1)&3).
// Guarantees rows r..r+7 at a fixed chunk hit 8 distinct 16B slots mod 128B.
__device__ __forceinline__ int smem_off(int row, int ch) {
    return (row << 6) + (((ch ^ ((row >> 1) & 3)) & 3) << 4);
}

// ------------------------- generic bf16x3 GEMM ------------------------------
// D[m][n] = sum_k A[m][k]*B[n][k]  (both operands K-major, pre-split hi/lo)
// MODE 0: plain tiles (blockIdx.x=n, y=m), epilogue -> bf16 hi/lo
// MODE 1: causal lower-triangle tiles (blockIdx.x=tile id, z=batch), -> fp32 * scale
// MODE 2: plain tiles + per-m-tile K limit (PV), -> fp32
template<int MODE>
__global__ void __launch_bounds__(256, 1)
gemm_k(const bf16* __restrict__ Ah, const bf16* __restrict__ Al, long long lda, long long aBS,
       const bf16* __restrict__ Bh, const bf16* __restrict__ Bl, long long ldb, long long bBS,
       float* __restrict__ Cf, bf16* __restrict__ Ch, bf16* __restrict__ Cl,
       long long ldc, long long cBS, int Kt, float scale)
{
    extern __shared__ char smem[];
    char* sAh = smem;
    char* sAl = smem + 1 * STAGES * TILE_BYTES;
    char* sBh = smem + 2 * STAGES * TILE_BYTES;
    char* sBl = smem + 3 * STAGES * TILE_BYTES;

    const long long bz = blockIdx.z;
    Ah += bz * aBS;  Al += bz * aBS;
    Bh += bz * bBS;  Bl += bz * bBS;
    if (Cf) Cf += bz * cBS;
    if (Ch) { Ch += bz * cBS; Cl += bz * cBS; }

    int tm, tn, kIters;
    if (MODE == 1) {
        int t = blockIdx.x, ib = 0;
        while ((ib + 1) * (ib + 2) / 2 <= t) ib++;
        int jb = t - ib * (ib + 1) / 2;
        tm = ib * BM; tn = jb * BN; kIters = Kt / BK;
    } else {
        tn = blockIdx.x * BN; tm = blockIdx.y * BM;
        kIters = (MODE == 2) ? (int)((blockIdx.y + 1) * BM) / BK : Kt / BK;
    }

    const int tid  = threadIdx.x;
    const int lane = tid & 31;
    const int warp = tid >> 5;
    const int wm   = warp >> 2;   // 0..1  (64 rows each)
    const int wn   = warp & 3;    // 0..3  (32 cols each)

    auto load_stage = [&](int st, int kOff) {
        char* dAh = sAh + st * TILE_BYTES;
        char* dAl = sAl + st * TILE_BYTES;
        char* dBh = sBh + st * TILE_BYTES;
        char* dBl = sBl + st * TILE_BYTES;
#pragma unroll
        for (int i = 0; i < 2; i++) {
            int idx = tid + (i << 8);
            int row = idx >> 2, ch = idx & 3;
            int so = smem_off(row, ch);
            size_t ga = (size_t)(tm + row) * lda + kOff + (ch << 3);
            size_t gb = (size_t)(tn + row) * ldb + kOff + (ch << 3);
            cp16(dAh + so, Ah + ga);
            cp16(dAl + so, Al + ga);
            cp16(dBh + so, Bh + gb);
            cp16(dBl + so, Bl + gb);
        }
    };

#pragma unroll
    for (int s = 0; s < STAGES - 1; s++) {
        if (s < kIters) load_stage(s, s * BK);
        asm volatile("cp.async.commit_group;\n" ::);
    }

    float acc[4][4][4];
#pragma unroll
    for (int a = 0; a < 4; a++)
#pragma unroll
        for (int b = 0; b < 4; b++)
#pragma unroll
            for (int c = 0; c < 4; c++) acc[a][b][c] = 0.f;

    for (int kb = 0; kb < kIters; kb++) {
        asm volatile("cp.async.wait_group 1;\n" ::);
        __syncthreads();
        int nk = kb + STAGES - 1;
        if (nk < kIters) load_stage(nk % STAGES, nk * BK);
        asm volatile("cp.async.commit_group;\n" ::);

        int st = kb % STAGES;
        const char* cAh = sAh + st * TILE_BYTES;
        const char* cAl = sAl + st * TILE_BYTES;
        const char* cBh = sBh + st * TILE_BYTES;
        const char* cBl = sBl + st * TILE_BYTES;

#pragma unroll
        for (int ks = 0; ks < 2; ks++) {
            const int k0 = ks * 16;
            uint32_t ah[4][4], al[4][4];
#pragma unroll
            for (int mi = 0; mi < 4; mi++) {
                int r  = wm * 64 + mi * 16 + (lane & 15);
                int ch = (k0 >> 3) + (lane >> 4);
                int so = smem_off(r, ch);
                ldsm4(ah[mi], cAh + so);
                ldsm4(al[mi], cAl + so);
            }
            uint32_t bh[4][2], bl[4][2];
#pragma unroll
            for (int pr = 0; pr < 2; pr++) {
                int n0 = wn * 32 + pr * 16;
                int r  = n0 + (lane & 7) + (((lane >> 4) & 1) << 3);
                int ch = (k0 >> 3) + ((lane >> 3) & 1);
                int so = smem_off(r, ch);
                uint32_t t4[4];
                ldsm4(t4, cBh + so);
                bh[pr*2][0] = t4[0]; bh[pr*2][1] = t4[1];
                bh[pr*2+1][0] = t4[2]; bh[pr*2+1][1] = t4[3];
                ldsm4(t4, cBl + so);
                bl[pr*2][0] = t4[0]; bl[pr*2][1] = t4[1];
                bl[pr*2+1][0] = t4[2]; bl[pr*2+1][1] = t4[3];
            }
#pragma unroll
            for (int mi = 0; mi < 4; mi++)
#pragma unroll
                for (int ni = 0; ni < 4; ni++) {
                    mma_bf16(acc[mi][ni], ah[mi], bh[ni]);
                    mma_bf16(acc[mi][ni], ah[mi], bl[ni]);
                    mma_bf16(acc[mi][ni], al[mi], bh[ni]);
                }
        }
        __syncthreads();
    }

    // epilogue
    const int g  = lane >> 2;
    const int tq = lane & 3;
#pragma unroll
    for (int mi = 0; mi < 4; mi++) {
#pragma unroll
        for (int ni = 0; ni < 4; ni++) {
            const float* c = acc[mi][ni];
            int c0 = tn + wn * 32 + ni * 8 + tq * 2;
#pragma unroll
            for (int h = 0; h < 2; h++) {
                int r = tm + wm * 64 + mi * 16 + g + h * 8;
                float v0 = c[h * 2 + 0], v1 = c[h * 2 + 1];
                if (MODE == 0) {
                    bf16 h0 = __float2bfloat16(v0), h1 = __float2bfloat16(v1);
                    __nv_bfloat162 hv; hv.x = h0; hv.y = h1;
                    *(__nv_bfloat162*)&Ch[(size_t)r * ldc + c0] = hv;
                    __nv_bfloat162 lv;
                    lv.x = __float2bfloat16(v0 - __bfloat162float(h0));
                    lv.y = __float2bfloat16(v1 - __bfloat162float(h1));
                    *(__nv_bfloat162*)&Cl[(size_t)r * ldc + c0] = lv;
                } else if (MODE == 1) {
                    float2 o; o.x = v0 * scale; o.y = v1 * scale;
                    *(float2*)&Cf[(size_t)r * ldc + c0] = o;
                } else {
                    float2 o; o.x = v0; o.y = v1;
                    *(float2*)&Cf[(size_t)r * ldc + c0] = o;
                }
            }
        }
    }
}

// ------------------------- fp32 -> bf16 hi/lo split -------------------------
__global__ void split_k(const float* __restrict__ in, bf16* __restrict__ hi,
                        bf16* __restrict__ lo, int n)
{
    int i = (blockIdx.x * 256 + threadIdx.x) * 4;
    if (i >= n) return;
    float4 v = *(const float4*)(in + i);
    bf16 h0 = __float2bfloat16(v.x), h1 = __float2bfloat16(v.y);
    bf16 h2 = __float2bfloat16(v.z), h3 = __float2bfloat16(v.w);
    __nv_bfloat162 a; a.x = h0; a.y = h1;
    __nv_bfloat162 b; b.x = h2; b.y = h3;
    *(__nv_bfloat162*)(hi + i)     = a;
    *(__nv_bfloat162*)(hi + i + 2) = b;
    __nv_bfloat162 c; c.x = __float2bfloat16(v.x - __bfloat162float(h0));
                      c.y = __float2bfloat16(v.y - __bfloat162float(h1));
    __nv_bfloat162 d; d.x = __float2bfloat16(v.z - __bfloat162float(h2));
                      d.y = __float2bfloat16(v.w - __bfloat162float(h3));
    *(__nv_bfloat162*)(lo + i)     = c;
    *(__nv_bfloat162*)(lo + i + 2) = d;
}

// ------------------------- causal row softmax -> P hi/lo --------------------
__global__ void __launch_bounds__(256) softmax_k(const float* __restrict__ S,
                                                 bf16* __restrict__ Ph,
                                                 bf16* __restrict__ Pl)
{
    __shared__ float buf[SEQ];
    __shared__ float red[8];
    int row = blockIdx.x;
    int b = row >> 11, i = row & 2047;
    int L = i + 1;
    size_t off = ((size_t)b << 22) + ((size_t)i << 11);
    const float* s = S + off;
    int t = threadIdx.x;

    float m = -3.4e38f;
    for (int j = t; j < L; j += 256) { float v = s[j]; buf[j] = v; m = fmaxf(m, v); }
#pragma unroll
    for (int o = 16; o; o >>= 1) m = fmaxf(m, __shfl_xor_sync(0xffffffffu, m, o));
    if ((t & 31) == 0) red[t >> 5] = m;
    __syncthreads();
    float bm = fmaxf(fmaxf(fmaxf(red[0], red[1]), fmaxf(red[2], red[3])),
                     fmaxf(fmaxf(red[4], red[5]), fmaxf(red[6], red[7])));

    float sum = 0.f;
    for (int j = t; j < L; j += 256) { float p = __expf(buf[j] - bm); buf[j] = p; sum += p; }
#pragma unroll
    for (int o = 16; o; o >>= 1) sum += __shfl_xor_sync(0xffffffffu, sum, o);
    __syncthreads();
    if ((t & 31) == 0) red[t >> 5] = sum;
    __syncthreads();
    float tot = red[0] + red[1] + red[2] + red[3] + red[4] + red[5] + red[6] + red[7];
    float inv = 1.f / tot;

    int Lpad = (L + 127) & ~127;   // zero-fill to tile boundary for PV K-limit
    for (int j = t; j < Lpad; j += 256) {
        float v = (j < L) ? buf[j] * inv : 0.f;
        bf16 h = __float2bfloat16(v);
        Ph[off + j] = h;
        Pl[off + j] = __float2bfloat16(v - __bfloat162float(h));
    }
}

// ------------------------- host orchestration -------------------------------
extern "C" void kernel_launch(void* const* d_in, const int* in_sizes, int n_in,
                              void* d_out, int out_size)
{
    const float* x  = (const float*)d_in[0];
    const float* Wq = (const float*)d_in[1];
    const float* Wk = (const float*)d_in[2];
    const float* Wv = (const float*)d_in[3];
    float* out = (float*)d_out;

    bf16 *Xh,*Xl,*Wqh,*Wql,*Wkh,*Wkl,*Wvh,*Wvl,*Qh,*Ql,*Kh,*Kl,*Vth,*Vtl,*Ph,*Pl;
    float* Sb;
    cudaGetSymbolAddress((void**)&Xh,  g_Xh);  cudaGetSymbolAddress((void**)&Xl,  g_Xl);
    cudaGetSymbolAddress((void**)&Wqh, g_Wqh); cudaGetSymbolAddress((void**)&Wql, g_Wql);
    cudaGetSymbolAddress((void**)&Wkh, g_Wkh); cudaGetSymbolAddress((void**)&Wkl, g_Wkl);
    cudaGetSymbolAddress((void**)&Wvh, g_Wvh); cudaGetSymbolAddress((void**)&Wvl, g_Wvl);
    cudaGetSymbolAddress((void**)&Qh,  g_Qh);  cudaGetSymbolAddress((void**)&Ql,  g_Ql);
    cudaGetSymbolAddress((void**)&Kh,  g_Kh);  cudaGetSymbolAddress((void**)&Kl,  g_Kl);
    cudaGetSymbolAddress((void**)&Vth, g_Vth); cudaGetSymbolAddress((void**)&Vtl, g_Vtl);
    cudaGetSymbolAddress((void**)&Ph,  g_Ph);  cudaGetSymbolAddress((void**)&Pl,  g_Pl);
    cudaGetSymbolAddress((void**)&Sb,  g_S);

    cudaFuncSetAttribute(gemm_k<0>, cudaFuncAttributeMaxDynamicSharedMemorySize, SMEM_BYTES);
    cudaFuncSetAttribute(gemm_k<1>, cudaFuncAttributeMaxDynamicSharedMemorySize, SMEM_BYTES);
    cudaFuncSetAttribute(gemm_k<2>, cudaFuncAttributeMaxDynamicSharedMemorySize, SMEM_BYTES);

    const int nX = MTOT * DM, nW = DM * DM;
    split_k<<<nX / 4 / 256, 256>>>(x,  Xh,  Xl,  nX);
    split_k<<<nW / 4 / 256, 256>>>(Wq, Wqh, Wql, nW);
    split_k<<<nW / 4 / 256, 256>>>(Wk, Wkh, Wkl, nW);
    split_k<<<nW / 4 / 256, 256>>>(Wv, Wvh, Wvl, nW);

    dim3 blk(256);
    // Q = X @ Wq^T  -> [8192,1024] bf16 hi/lo
    gemm_k<0><<<dim3(DM / BN, MTOT / BM, 1), blk, SMEM_BYTES>>>(
        Xh, Xl, DM, 0, Wqh, Wql, DM, 0, nullptr, Qh, Ql, DM, 0, DM, 1.f);
    // K = X @ Wk^T
    gemm_k<0><<<dim3(DM / BN, MTOT / BM, 1), blk, SMEM_BYTES>>>(
        Xh, Xl, DM, 0, Wkh, Wkl, DM, 0, nullptr, Kh, Kl, DM, 0, DM, 1.f);
    // Vt[v, bs] = Wv @ X^T  -> [1024, 8192] bf16 hi/lo (K-major B for PV GEMM)
    gemm_k<0><<<dim3(MTOT / BN, DM / BM, 1), blk, SMEM_BYTES>>>(
        Wvh, Wvl, DM, 0, Xh, Xl, DM, 0, nullptr, Vth, Vtl, MTOT, 0, DM, 1.f);
    // S = (Q @ K^T) / 32, causal lower-triangle tiles only (136 per batch)
    gemm_k<1><<<dim3(136, 1, NB), blk, SMEM_BYTES>>>(
        Qh, Ql, DM, (long long)SEQ * DM, Kh, Kl, DM, (long long)SEQ * DM,
        Sb, nullptr, nullptr, SEQ, (long long)SEQ * SEQ, DM, 0.03125f);
    // row softmax (reads only j<=i) -> P hi/lo, zero-filled to 128 boundary
    softmax_k<<<MTOT, 256>>>(Sb, Ph, Pl);
    // O = P @ V  (B = Vt, per-batch column offset; K limited to (mblk+1)*128)
    gemm_k<2><<<dim3(DM / BN, SEQ / BM, NB), blk, SMEM_BYTES>>>(
        Ph, Pl, SEQ, (long long)SEQ * SEQ, Vth, Vtl, MTOT, (long long)SEQ,
        out, nullptr, nullptr, DM, (long long)SEQ * DM, SEQ, 1.f);
}

// round 4
// speedup vs baseline: 1.0597x; 1.0597x over previous
#include <cuda_runtime.h>
#include <cuda_bf16.h>
#include <cstdint>

typedef __nv_bfloat16 bf16;

#define NB   4
#define SEQ  2048
#define DM   1024
#define MTOT (NB*SEQ)          // 8192
#define NW   (DM*DM)

#define BM 128
#define BN 128
#define BK 32
#define STAGES 3
#define TILE_BYTES (BM*BK*2)               // 8192 B per operand tile
#define SMEM_BYTES (STAGES*4*TILE_BYTES)   // 98304 B

// ------------------------- scratch (__device__ globals; no allocs) ----------
__device__ bf16  g_Xh[MTOT*DM],  g_Xl[MTOT*DM];
__device__ bf16  g_Wqh[NW],      g_Wql[NW];
__device__ bf16  g_Wkh[NW],      g_Wkl[NW];
__device__ bf16  g_Wvh[NW],      g_Wvl[NW];
__device__ bf16  g_Qh[MTOT*DM],  g_Ql[MTOT*DM];
__device__ bf16  g_Kh[MTOT*DM],  g_Kl[MTOT*DM];
__device__ bf16  g_Vth[DM*MTOT], g_Vtl[DM*MTOT];
__device__ float g_S[(size_t)MTOT*SEQ];
__device__ bf16  g_Ph[(size_t)MTOT*SEQ], g_Pl[(size_t)MTOT*SEQ];

// ------------------------- PTX helpers -------------------------------------
__device__ __forceinline__ void cp16(void* s, const void* g) {
    uint32_t sa = (uint32_t)__cvta_generic_to_shared(s);
    asm volatile("cp.async.cg.shared.global [%0], [%1], 16;\n" :: "r"(sa), "l"(g));
}
__device__ __forceinline__ void ldsm4(uint32_t* r, const void* p) {
    uint32_t a = (uint32_t)__cvta_generic_to_shared(p);
    asm volatile("ldmatrix.sync.aligned.m8n8.x4.shared.b16 {%0,%1,%2,%3}, [%4];\n"
                 : "=r"(r[0]), "=r"(r[1]), "=r"(r[2]), "=r"(r[3]) : "r"(a));
}
__device__ __forceinline__ void mma_bf16(float* c, const uint32_t* a, const uint32_t* b) {
    asm volatile("mma.sync.aligned.m16n8k16.row.col.f32.bf16.bf16.f32 "
                 "{%0,%1,%2,%3}, {%4,%5,%6,%7}, {%8,%9}, {%0,%1,%2,%3};\n"
                 : "+f"(c[0]), "+f"(c[1]), "+f"(c[2]), "+f"(c[3])
                 : "r"(a[0]), "r"(a[1]), "r"(a[2]), "r"(a[3]), "r"(b[0]), "r"(b[1]));
}
// 16B-chunk XOR swizzle: row stride 64B, chunk' = chunk ^ ((row>>1)&3).
__device__ __forceinline__ int smem_off(int row, int ch) {
    return (row << 6) + (((ch ^ ((row >> 1) & 3)) & 3) << 4);
}

// ------------------------- shared bf16x3 GEMM core --------------------------
// D[m][n] = sum_k A[m][k]*B[n][k]  (both K-major, pre-split hi/lo)
// OUT 0: bf16 hi/lo outputs   OUT 1: fp32 * scale
template<int OUT>
__device__ __forceinline__ void gemm_core(
    const bf16* __restrict__ Ah, const bf16* __restrict__ Al, int lda,
    const bf16* __restrict__ Bh, const bf16* __restrict__ Bl, int ldb,
    float* __restrict__ Cf, bf16* __restrict__ Ch, bf16* __restrict__ Cl,
    int ldc, int tm, int tn, int kIters, float scale, char* smem)
{
    char* sAh = smem;
    char* sAl = smem + 1 * STAGES * TILE_BYTES;
    char* sBh = smem + 2 * STAGES * TILE_BYTES;
    char* sBl = smem + 3 * STAGES * TILE_BYTES;

    const int tid  = threadIdx.x;
    const int lane = tid & 31;
    const int warp = tid >> 5;
    const int wm   = warp >> 2;   // 0..1  (64 rows each)
    const int wn   = warp & 3;    // 0..3  (32 cols each)

    auto load_stage = [&](int st, int kOff) {
        char* dAh = sAh + st * TILE_BYTES;
        char* dAl = sAl + st * TILE_BYTES;
        char* dBh = sBh + st * TILE_BYTES;
        char* dBl = sBl + st * TILE_BYTES;
#pragma unroll
        for (int i = 0; i < 2; i++) {
            int idx = tid + (i << 8);
            int row = idx >> 2, ch = idx & 3;
            int so = smem_off(row, ch);
            size_t ga = (size_t)(tm + row) * lda + kOff + (ch << 3);
            size_t gb = (size_t)(tn + row) * ldb + kOff + (ch << 3);
            cp16(dAh + so, Ah + ga);
            cp16(dAl + so, Al + ga);
            cp16(dBh + so, Bh + gb);
            cp16(dBl + so, Bl + gb);
        }
    };

#pragma unroll
    for (int s = 0; s < STAGES - 1; s++) {
        if (s < kIters) load_stage(s, s * BK);
        asm volatile("cp.async.commit_group;\n" ::);
    }

    float acc[4][4][4];
#pragma unroll
    for (int a = 0; a < 4; a++)
#pragma unroll
        for (int b = 0; b < 4; b++)
#pragma unroll
            for (int c = 0; c < 4; c++) acc[a][b][c] = 0.f;

    for (int kb = 0; kb < kIters; kb++) {
        asm volatile("cp.async.wait_group 1;\n" ::);
        __syncthreads();
        int nk = kb + STAGES - 1;
        if (nk < kIters) load_stage(nk % STAGES, nk * BK);
        asm volatile("cp.async.commit_group;\n" ::);

        int st = kb % STAGES;
        const char* cAh = sAh + st * TILE_BYTES;
        const char* cAl = sAl + st * TILE_BYTES;
        const char* cBh = sBh + st * TILE_BYTES;
        const char* cBl = sBl + st * TILE_BYTES;

#pragma unroll
        for (int ks = 0; ks < 2; ks++) {
            const int k0 = ks * 16;
            uint32_t ah[4][4], al[4][4];
#pragma unroll
            for (int mi = 0; mi < 4; mi++) {
                int r  = wm * 64 + mi * 16 + (lane & 15);
                int ch = (k0 >> 3) + (lane >> 4);
                int so = smem_off(r, ch);
                ldsm4(ah[mi], cAh + so);
                ldsm4(al[mi], cAl + so);
            }
            uint32_t bh[4][2], bl[4][2];
#pragma unroll
            for (int pr = 0; pr < 2; pr++) {
                int n0 = wn * 32 + pr * 16;
                int r  = n0 + (lane & 7) + (((lane >> 4) & 1) << 3);
                int ch = (k0 >> 3) + ((lane >> 3) & 1);
                int so = smem_off(r, ch);
                uint32_t t4[4];
                ldsm4(t4, cBh + so);
                bh[pr*2][0] = t4[0]; bh[pr*2][1] = t4[1];
                bh[pr*2+1][0] = t4[2]; bh[pr*2+1][1] = t4[3];
                ldsm4(t4, cBl + so);
                bl[pr*2][0] = t4[0]; bl[pr*2][1] = t4[1];
                bl[pr*2+1][0] = t4[2]; bl[pr*2+1][1] = t4[3];
            }
            // term-major ordering: 16 independent HMMAs per batch
#pragma unroll
            for (int mi = 0; mi < 4; mi++)
#pragma unroll
                for (int ni = 0; ni < 4; ni++)
                    mma_bf16(acc[mi][ni], ah[mi], bh[ni]);
#pragma unroll
            for (int mi = 0; mi < 4; mi++)
#pragma unroll
                for (int ni = 0; ni < 4; ni++)
                    mma_bf16(acc[mi][ni], ah[mi], bl[ni]);
#pragma unroll
            for (int mi = 0; mi < 4; mi++)
#pragma unroll
                for (int ni = 0; ni < 4; ni++)
                    mma_bf16(acc[mi][ni], al[mi], bh[ni]);
        }
        __syncthreads();
    }

    // epilogue
    const int g  = lane >> 2;
    const int tq = lane & 3;
#pragma unroll
    for (int mi = 0; mi < 4; mi++) {
#pragma unroll
        for (int ni = 0; ni < 4; ni++) {
            const float* c = acc[mi][ni];
            int c0 = tn + wn * 32 + ni * 8 + tq * 2;
#pragma unroll
            for (int h = 0; h < 2; h++) {
                int r = tm + wm * 64 + mi * 16 + g + h * 8;
                float v0 = c[h * 2 + 0], v1 = c[h * 2 + 1];
                if (OUT == 0) {
                    bf16 h0 = __float2bfloat16(v0), h1 = __float2bfloat16(v1);
                    __nv_bfloat162 hv; hv.x = h0; hv.y = h1;
                    *(__nv_bfloat162*)&Ch[(size_t)r * ldc + c0] = hv;
                    __nv_bfloat162 lv;
                    lv.x = __float2bfloat16(v0 - __bfloat162float(h0));
                    lv.y = __float2bfloat16(v1 - __bfloat162float(h1));
                    *(__nv_bfloat162*)&Cl[(size_t)r * ldc + c0] = lv;
                } else {
                    float2 o; o.x = v0 * scale; o.y = v1 * scale;
                    *(float2*)&Cf[(size_t)r * ldc + c0] = o;
                }
            }
        }
    }
}

// ------------------------- GEMM kernels -------------------------------------
// Merged projections: z=0 Q, z=1 K, z=2 Vt (role-swapped tiles)
__global__ void __launch_bounds__(256, 1) proj_k()
{
    extern __shared__ char smem[];
    int z = blockIdx.z;
    if (z == 0) {
        gemm_core<0>(g_Xh, g_Xl, DM, g_Wqh, g_Wql, DM,
                     nullptr, g_Qh, g_Ql, DM,
                     blockIdx.y * BM, blockIdx.x * BN, DM / BK, 1.f, smem);
    } else if (z == 1) {
        gemm_core<0>(g_Xh, g_Xl, DM, g_Wkh, g_Wkl, DM,
                     nullptr, g_Kh, g_Kl, DM,
                     blockIdx.y * BM, blockIdx.x * BN, DM / BK, 1.f, smem);
    } else {
        // Vt = Wv @ X^T -> [1024, 8192]; tm over DM (bx<8), tn over MTOT (by<64)
        gemm_core<0>(g_Wvh, g_Wvl, DM, g_Xh, g_Xl, DM,
                     nullptr, g_Vth, g_Vtl, MTOT,
                     blockIdx.x * BM, blockIdx.y * BN, DM / BK, 1.f, smem);
    }
}

// Causal lower-triangle score tiles: S = (Q K^T)/32
__global__ void __launch_bounds__(256, 1) score_k()
{
    extern __shared__ char smem[];
    int b = blockIdx.z;
    int t = blockIdx.x, ib = 0;
    while ((ib + 1) * (ib + 2) / 2 <= t) ib++;
    int jb = t - ib * (ib + 1) / 2;
    size_t qo = (size_t)b * SEQ * DM;
    gemm_core<1>(g_Qh + qo, g_Ql + qo, DM, g_Kh + qo, g_Kl + qo, DM,
                 g_S + (size_t)b * SEQ * SEQ, nullptr, nullptr, SEQ,
                 ib * BM, jb * BN, DM / BK, 0.03125f, smem);
}

// O = P @ V, per-m-tile K limit
__global__ void __launch_bounds__(256, 1) pv_k(float* __restrict__ out)
{
    extern __shared__ char smem[];
    int b = blockIdx.z;
    size_t po = (size_t)b * SEQ * SEQ;
    gemm_core<1>(g_Ph + po, g_Pl + po, SEQ,
                 g_Vth + (size_t)b * SEQ, g_Vtl + (size_t)b * SEQ, MTOT,
                 out + (size_t)b * SEQ * DM, nullptr, nullptr, DM,
                 blockIdx.y * BM, blockIdx.x * BN,
                 (int)(blockIdx.y + 1) * BM / BK, 1.f, smem);
}

// ------------------------- splits -------------------------------------------
__device__ __forceinline__ void split4(const float* in, bf16* hi, bf16* lo, int i) {
    float4 v = *(const float4*)(in + i);
    bf16 h0 = __float2bfloat16(v.x), h1 = __float2bfloat16(v.y);
    bf16 h2 = __float2bfloat16(v.z), h3 = __float2bfloat16(v.w);
    __nv_bfloat162 a; a.x = h0; a.y = h1;
    __nv_bfloat162 b; b.x = h2; b.y = h3;
    *(__nv_bfloat162*)(hi + i)     = a;
    *(__nv_bfloat162*)(hi + i + 2) = b;
    __nv_bfloat162 c; c.x = __float2bfloat16(v.x - __bfloat162float(h0));
                      c.y = __float2bfloat16(v.y - __bfloat162float(h1));
    __nv_bfloat162 d; d.x = __float2bfloat16(v.z - __bfloat162float(h2));
                      d.y = __float2bfloat16(v.w - __bfloat162float(h3));
    *(__nv_bfloat162*)(lo + i)     = c;
    *(__nv_bfloat162*)(lo + i + 2) = d;
}
__global__ void splitX_k(const float* __restrict__ x) {
    int i = (blockIdx.x * 256 + threadIdx.x) * 4;
    if (i < MTOT * DM) split4(x, g_Xh, g_Xl, i);
}
__global__ void splitW_k(const float* __restrict__ wq,
                         const float* __restrict__ wk,
                         const float* __restrict__ wv) {
    int i = (blockIdx.x * 256 + threadIdx.x) * 4;
    if (i < NW)              split4(wq, g_Wqh, g_Wql, i);
    else if (i < 2 * NW)     split4(wk + (i - NW),     g_Wkh + (i - NW),     g_Wkl + (i - NW),     0),
                             (void)0;
    else if (i < 3 * NW)     split4(wv + (i - 2 * NW), g_Wvh + (i - 2 * NW), g_Wvl + (i - 2 * NW), 0);
}

// ------------------------- causal row softmax -> P hi/lo --------------------
__global__ void __launch_bounds__(256) softmax_k(const float* __restrict__ S,
                                                 bf16* __restrict__ Ph,
                                                 bf16* __restrict__ Pl)
{
    __shared__ float buf[SEQ];
    __shared__ float red[8];
    int row = blockIdx.x;
    int b = row >> 11, i = row & 2047;
    int L = i + 1;
    size_t off = ((size_t)b << 22) + ((size_t)i << 11);
    const float* s = S + off;
    int t = threadIdx.x;

    float m = -3.4e38f;
    for (int j = t; j < L; j += 256) { float v = s[j]; buf[j] = v; m = fmaxf(m, v); }
#pragma unroll
    for (int o = 16; o; o >>= 1) m = fmaxf(m, __shfl_xor_sync(0xffffffffu, m, o));
    if ((t & 31) == 0) red[t >> 5] = m;
    __syncthreads();
    float bm = fmaxf(fmaxf(fmaxf(red[0], red[1]), fmaxf(red[2], red[3])),
                     fmaxf(fmaxf(red[4], red[5]), fmaxf(red[6], red[7])));

    float sum = 0.f;
    for (int j = t; j < L; j += 256) { float p = __expf(buf[j] - bm); buf[j] = p; sum += p; }
#pragma unroll
    for (int o = 16; o; o >>= 1) sum += __shfl_xor_sync(0xffffffffu, sum, o);
    __syncthreads();
    if ((t & 31) == 0) red[t >> 5] = sum;
    __syncthreads();
    float tot = red[0] + red[1] + red[2] + red[3] + red[4] + red[5] + red[6] + red[7];
    float inv = 1.f / tot;

    int Lpad = (L + 127) & ~127;   // zero-fill to tile boundary for PV K-limit
    for (int j = t; j < Lpad; j += 256) {
        float v = (j < L) ? buf[j] * inv : 0.f;
        bf16 h = __float2bfloat16(v);
        Ph[off + j] = h;
        Pl[off + j] = __float2bfloat16(v - __bfloat162float(h));
    }
}

// ------------------------- host orchestration -------------------------------
extern "C" void kernel_launch(void* const* d_in, const int* in_sizes, int n_in,
                              void* d_out, int out_size)
{
    const float* x  = (const float*)d_in[0];
    const float* Wq = (const float*)d_in[1];
    const float* Wk = (const float*)d_in[2];
    const float* Wv = (const float*)d_in[3];
    float* out = (float*)d_out;

    bf16 *Ph, *Pl;  float* Sb;
    cudaGetSymbolAddress((void**)&Ph, g_Ph);
    cudaGetSymbolAddress((void**)&Pl, g_Pl);
    cudaGetSymbolAddress((void**)&Sb, g_S);

    cudaFuncSetAttribute(proj_k,  cudaFuncAttributeMaxDynamicSharedMemorySize, SMEM_BYTES);
    cudaFuncSetAttribute(score_k, cudaFuncAttributeMaxDynamicSharedMemorySize, SMEM_BYTES);
    cudaFuncSetAttribute(pv_k,    cudaFuncAttributeMaxDynamicSharedMemorySize, SMEM_BYTES);

    dim3 blk(256);
    splitX_k<<<MTOT * DM / 4 / 256, 256>>>(x);                       // launch 0
    splitW_k<<<3 * NW / 4 / 256, 256>>>(Wq, Wk, Wv);                 // launch 1
    proj_k<<<dim3(8, 64, 3), blk, SMEM_BYTES>>>();                   // launch 2
    score_k<<<dim3(136, 1, NB), blk, SMEM_BYTES>>>();                // launch 3
    softmax_k<<<MTOT, 256>>>(Sb, Ph, Pl);                            // launch 4
    pv_k<<<dim3(DM / BN, SEQ / BM, NB), blk, SMEM_BYTES>>>(out);     // launch 5 (ncu target)
}

// round 6
// speedup vs baseline: 1.2063x; 1.1383x over previous
#include <cuda_runtime.h>
#include <cuda_bf16.h>
#include <cstdint>

typedef __nv_bfloat16 bf16;

#define NB   4
#define SEQ  2048
#define DM   1024
#define MTOT (NB*SEQ)          // 8192
#define NW   (DM*DM)

#define BM 128
#define BN 128
#define BK 32
#define STAGES 2
#define TILE_BYTES (BM*BK*2)               // 8192 B per operand tile
#define SMEM_BYTES (STAGES*4*TILE_BYTES)   // 65536 B -> 2 CTAs/SM

// ------------------------- scratch (__device__ globals; no allocs) ----------
__device__ bf16  g_Xh[MTOT*DM],  g_Xl[MTOT*DM];
__device__ bf16  g_Wqh[NW],      g_Wql[NW];
__device__ bf16  g_Wkh[NW],      g_Wkl[NW];
__device__ bf16  g_Wvh[NW],      g_Wvl[NW];
__device__ bf16  g_Qh[MTOT*DM],  g_Ql[MTOT*DM];
__device__ bf16  g_Kh[MTOT*DM],  g_Kl[MTOT*DM];
__device__ bf16  g_Vth[DM*MTOT], g_Vtl[DM*MTOT];
__device__ float g_S[(size_t)MTOT*SEQ];
__device__ bf16  g_Ph[(size_t)MTOT*SEQ], g_Pl[(size_t)MTOT*SEQ];

// ------------------------- PTX helpers -------------------------------------
__device__ __forceinline__ void cp16(void* s, const void* g) {
    uint32_t sa = (uint32_t)__cvta_generic_to_shared(s);
    asm volatile("cp.async.cg.shared.global [%0], [%1], 16;\n" :: "r"(sa), "l"(g));
}
__device__ __forceinline__ void ldsm4(uint32_t* r, const void* p) {
    uint32_t a = (uint32_t)__cvta_generic_to_shared(p);
    asm volatile("ldmatrix.sync.aligned.m8n8.x4.shared.b16 {%0,%1,%2,%3}, [%4];\n"
                 : "=r"(r[0]), "=r"(r[1]), "=r"(r[2]), "=r"(r[3]) : "r"(a));
}
__device__ __forceinline__ void mma_bf16(float* c, const uint32_t* a, const uint32_t* b) {
    asm volatile("mma.sync.aligned.m16n8k16.row.col.f32.bf16.bf16.f32 "
                 "{%0,%1,%2,%3}, {%4,%5,%6,%7}, {%8,%9}, {%0,%1,%2,%3};\n"
                 : "+f"(c[0]), "+f"(c[1]), "+f"(c[2]), "+f"(c[3])
                 : "r"(a[0]), "r"(a[1]), "r"(a[2]), "r"(a[3]), "r"(b[0]), "r"(b[1]));
}
// 16B-chunk XOR swizzle: row stride 64B, chunk' = chunk ^ ((row>>1)&3).
__device__ __forceinline__ int smem_off(int row, int ch) {
    return (row << 6) + (((ch ^ ((row >> 1) & 3)) & 3) << 4);
}

// ------------------------- shared bf16x3 GEMM core --------------------------
// D[m][n] = sum_k A[m][k]*B[n][k]  (both K-major, pre-split hi/lo)
// OUT 0: bf16 hi/lo outputs   OUT 1: fp32 * scale
template<int OUT>
__device__ __forceinline__ void gemm_core(
    const bf16* __restrict__ Ah, const bf16* __restrict__ Al, int lda,
    const bf16* __restrict__ Bh, const bf16* __restrict__ Bl, int ldb,
    float* __restrict__ Cf, bf16* __restrict__ Ch, bf16* __restrict__ Cl,
    int ldc, int tm, int tn, int kIters, float scale, char* smem)
{
    char* sAh = smem;
    char* sAl = smem + 1 * STAGES * TILE_BYTES;
    char* sBh = smem + 2 * STAGES * TILE_BYTES;
    char* sBl = smem + 3 * STAGES * TILE_BYTES;

    const int tid  = threadIdx.x;
    const int lane = tid & 31;
    const int warp = tid >> 5;
    const int wm   = warp >> 2;   // 0..1  (64 rows each)
    const int wn   = warp & 3;    // 0..3  (32 cols each)

    auto load_stage = [&](int st, int kOff) {
        char* dAh = sAh + st * TILE_BYTES;
        char* dAl = sAl + st * TILE_BYTES;
        char* dBh = sBh + st * TILE_BYTES;
        char* dBl = sBl + st * TILE_BYTES;
#pragma unroll
        for (int i = 0; i < 2; i++) {
            int idx = tid + (i << 8);
            int row = idx >> 2, ch = idx & 3;
            int so = smem_off(row, ch);
            size_t ga = (size_t)(tm + row) * lda + kOff + (ch << 3);
            size_t gb = (size_t)(tn + row) * ldb + kOff + (ch << 3);
            cp16(dAh + so, Ah + ga);
            cp16(dAl + so, Al + ga);
            cp16(dBh + so, Bh + gb);
            cp16(dBl + so, Bl + gb);
        }
    };

    load_stage(0, 0);
    asm volatile("cp.async.commit_group;\n" ::);

    float acc[4][4][4];
#pragma unroll
    for (int a = 0; a < 4; a++)
#pragma unroll
        for (int b = 0; b < 4; b++)
#pragma unroll
            for (int c = 0; c < 4; c++) acc[a][b][c] = 0.f;

    for (int kb = 0; kb < kIters; kb++) {
        if (kb + 1 < kIters) load_stage((kb + 1) & 1, (kb + 1) * BK);
        asm volatile("cp.async.commit_group;\n" ::);
        asm volatile("cp.async.wait_group 1;\n" ::);   // stage kb resident
        __syncthreads();

        int st = kb & 1;
        const char* cAh = sAh + st * TILE_BYTES;
        const char* cAl = sAl + st * TILE_BYTES;
        const char* cBh = sBh + st * TILE_BYTES;
        const char* cBl = sBl + st * TILE_BYTES;

#pragma unroll
        for (int ks = 0; ks < 2; ks++) {
            const int k0 = ks * 16;
            uint32_t ah[4][4], al[4][4];
#pragma unroll
            for (int mi = 0; mi < 4; mi++) {
                int r  = wm * 64 + mi * 16 + (lane & 15);
                int ch = (k0 >> 3) + (lane >> 4);
                int so = smem_off(r, ch);
                ldsm4(ah[mi], cAh + so);
                ldsm4(al[mi], cAl + so);
            }
            // B fragments loaded & consumed per 16-col pair (8 live regs)
#pragma unroll
            for (int pr = 0; pr < 2; pr++) {
                int n0 = wn * 32 + pr * 16;
                int r  = n0 + (lane & 7) + (((lane >> 4) & 1) << 3);
                int ch = (k0 >> 3) + ((lane >> 3) & 1);
                int so = smem_off(r, ch);
                uint32_t bh[4], bl[4];
                ldsm4(bh, cBh + so);
                ldsm4(bl, cBl + so);
                const int n0i = pr * 2;
                // term-major: 8 independent HMMAs per batch
#pragma unroll
                for (int mi = 0; mi < 4; mi++) {
                    mma_bf16(acc[mi][n0i + 0], ah[mi], bh + 0);
                    mma_bf16(acc[mi][n0i + 1], ah[mi], bh + 2);
                }
#pragma unroll
                for (int mi = 0; mi < 4; mi++) {
                    mma_bf16(acc[mi][n0i + 0], ah[mi], bl + 0);
                    mma_bf16(acc[mi][n0i + 1], ah[mi], bl + 2);
                }
#pragma unroll
                for (int mi = 0; mi < 4; mi++) {
                    mma_bf16(acc[mi][n0i + 0], al[mi], bh + 0);
                    mma_bf16(acc[mi][n0i + 1], al[mi], bh + 2);
                }
            }
        }
        __syncthreads();
    }

    // epilogue
    const int g  = lane >> 2;
    const int tq = lane & 3;
#pragma unroll
    for (int mi = 0; mi < 4; mi++) {
#pragma unroll
        for (int ni = 0; ni < 4; ni++) {
            const float* c = acc[mi][ni];
            int c0 = tn + wn * 32 + ni * 8 + tq * 2;
#pragma unroll
            for (int h = 0; h < 2; h++) {
                int r = tm + wm * 64 + mi * 16 + g + h * 8;
                float v0 = c[h * 2 + 0], v1 = c[h * 2 + 1];
                if (OUT == 0) {
                    bf16 h0 = __float2bfloat16(v0), h1 = __float2bfloat16(v1);
                    __nv_bfloat162 hv; hv.x = h0; hv.y = h1;
                    *(__nv_bfloat162*)&Ch[(size_t)r * ldc + c0] = hv;
                    __nv_bfloat162 lv;
                    lv.x = __float2bfloat16(v0 - __bfloat162float(h0));
                    lv.y = __float2bfloat16(v1 - __bfloat162float(h1));
                    *(__nv_bfloat162*)&Cl[(size_t)r * ldc + c0] = lv;
                } else {
                    float2 o; o.x = v0 * scale; o.y = v1 * scale;
                    *(float2*)&Cf[(size_t)r * ldc + c0] = o;
                }
            }
        }
    }
}

// ------------------------- GEMM kernels -------------------------------------
// Merged projections: z=0 Q, z=1 K, z=2 Vt (role-swapped tiles)
__global__ void __launch_bounds__(256, 2) proj_k()
{
    extern __shared__ char smem[];
    int z = blockIdx.z;
    if (z == 0) {
        gemm_core<0>(g_Xh, g_Xl, DM, g_Wqh, g_Wql, DM,
                     nullptr, g_Qh, g_Ql, DM,
                     blockIdx.y * BM, blockIdx.x * BN, DM / BK, 1.f, smem);
    } else if (z == 1) {
        gemm_core<0>(g_Xh, g_Xl, DM, g_Wkh, g_Wkl, DM,
                     nullptr, g_Kh, g_Kl, DM,
                     blockIdx.y * BM, blockIdx.x * BN, DM / BK, 1.f, smem);
    } else {
        // Vt = Wv @ X^T -> [1024, 8192]; tm over DM (bx<8), tn over MTOT (by<64)
        gemm_core<0>(g_Wvh, g_Wvl, DM, g_Xh, g_Xl, DM,
                     nullptr, g_Vth, g_Vtl, MTOT,
                     blockIdx.x * BM, blockIdx.y * BN, DM / BK, 1.f, smem);
    }
}

// Causal lower-triangle score tiles: S = (Q K^T)/32
__global__ void __launch_bounds__(256, 2) score_k()
{
    extern __shared__ char smem[];
    int b = blockIdx.z;
    int t = blockIdx.x, ib = 0;
    while ((ib + 1) * (ib + 2) / 2 <= t) ib++;
    int jb = t - ib * (ib + 1) / 2;
    size_t qo = (size_t)b * SEQ * DM;
    gemm_core<1>(g_Qh + qo, g_Ql + qo, DM, g_Kh + qo, g_Kl + qo, DM,
                 g_S + (size_t)b * SEQ * SEQ, nullptr, nullptr, SEQ,
                 ib * BM, jb * BN, DM / BK, 0.03125f, smem);
}

// O = P @ V, per-m-tile K limit
__global__ void __launch_bounds__(256, 2) pv_k(float* __restrict__ out)
{
    extern __shared__ char smem[];
    int b = blockIdx.z;
    size_t po = (size_t)b * SEQ * SEQ;
    gemm_core<1>(g_Ph + po, g_Pl + po, SEQ,
                 g_Vth + (size_t)b * SEQ, g_Vtl + (size_t)b * SEQ, MTOT,
                 out + (size_t)b * SEQ * DM, nullptr, nullptr, DM,
                 blockIdx.y * BM, blockIdx.x * BN,
                 (int)(blockIdx.y + 1) * BM / BK, 1.f, smem);
}

// ------------------------- splits -------------------------------------------
__device__ __forceinline__ void split4(const float* in, bf16* hi, bf16* lo, int i) {
    float4 v = *(const float4*)(in + i);
    bf16 h0 = __float2bfloat16(v.x), h1 = __float2bfloat16(v.y);
    bf16 h2 = __float2bfloat16(v.z), h3 = __float2bfloat16(v.w);
    __nv_bfloat162 a; a.x = h0; a.y = h1;
    __nv_bfloat162 b; b.x = h2; b.y = h3;
    *(__nv_bfloat162*)(hi + i)     = a;
    *(__nv_bfloat162*)(hi + i + 2) = b;
    __nv_bfloat162 c; c.x = __float2bfloat16(v.x - __bfloat162float(h0));
                      c.y = __float2bfloat16(v.y - __bfloat162float(h1));
    __nv_bfloat162 d; d.x = __float2bfloat16(v.z - __bfloat162float(h2));
                      d.y = __float2bfloat16(v.w - __bfloat162float(h3));
    *(__nv_bfloat162*)(lo + i)     = c;
    *(__nv_bfloat162*)(lo + i + 2) = d;
}
__global__ void splitX_k(const float* __restrict__ x) {
    int i = (blockIdx.x * 256 + threadIdx.x) * 4;
    if (i < MTOT * DM) split4(x, g_Xh, g_Xl, i);
}
__global__ void splitW_k(const float* __restrict__ wq,
                         const float* __restrict__ wk,
                         const float* __restrict__ wv) {
    int i = (blockIdx.x * 256 + threadIdx.x) * 4;
    if (i < NW)          split4(wq, g_Wqh, g_Wql, i);
    else if (i < 2 * NW) split4(wk + (i - NW),     g_Wkh + (i - NW),     g_Wkl + (i - NW),     0);
    else if (i < 3 * NW) split4(wv + (i - 2 * NW), g_Wvh + (i - 2 * NW), g_Wvl + (i - 2 * NW), 0);
}

// ------------------------- causal row softmax -> P hi/lo --------------------
__global__ void __launch_bounds__(256) softmax_k(const float* __restrict__ S,
                                                 bf16* __restrict__ Ph,
                                                 bf16* __restrict__ Pl)
{
    __shared__ float buf[SEQ];
    __shared__ float red[8];
    int row = blockIdx.x;
    int b = row >> 11, i = row & 2047;
    int L = i + 1;
    size_t off = ((size_t)b << 22) + ((size_t)i << 11);
    const float* s = S + off;
    int t = threadIdx.x;

    float m = -3.4e38f;
    for (int j = t; j < L; j += 256) { float v = s[j]; buf[j] = v; m = fmaxf(m, v); }
#pragma unroll
    for (int o = 16; o; o >>= 1) m = fmaxf(m, __shfl_xor_sync(0xffffffffu, m, o));
    if ((t & 31) == 0) red[t >> 5] = m;
    __syncthreads();
    float bm = fmaxf(fmaxf(fmaxf(red[0], red[1]), fmaxf(red[2], red[3])),
                     fmaxf(fmaxf(red[4], red[5]), fmaxf(red[6], red[7])));

    float sum = 0.f;
    for (int j = t; j < L; j += 256) { float p = __expf(buf[j] - bm); buf[j] = p; sum += p; }
#pragma unroll
    for (int o = 16; o; o >>= 1) sum += __shfl_xor_sync(0xffffffffu, sum, o);
    __syncthreads();
    if ((t & 31) == 0) red[t >> 5] = sum;
    __syncthreads();
    float tot = red[0] + red[1] + red[2] + red[3] + red[4] + red[5] + red[6] + red[7];
    float inv = 1.f / tot;

    int Lpad = (L + 127) & ~127;   // zero-fill to tile boundary for PV K-limit
    for (int j = t; j < Lpad; j += 256) {
        float v = (j < L) ? buf[j] * inv : 0.f;
        bf16 h = __float2bfloat16(v);
        Ph[off + j] = h;
        Pl[off + j] = __float2bfloat16(v - __bfloat162float(h));
    }
}

// ------------------------- host orchestration -------------------------------
extern "C" void kernel_launch(void* const* d_in, const int* in_sizes, int n_in,
                              void* d_out, int out_size)
{
    const float* x  = (const float*)d_in[0];
    const float* Wq = (const float*)d_in[1];
    const float* Wk = (const float*)d_in[2];
    const float* Wv = (const float*)d_in[3];
    float* out = (float*)d_out;

    bf16 *Ph, *Pl;  float* Sb;
    cudaGetSymbolAddress((void**)&Ph, g_Ph);
    cudaGetSymbolAddress((void**)&Pl, g_Pl);
    cudaGetSymbolAddress((void**)&Sb, g_S);

    cudaFuncSetAttribute(proj_k,  cudaFuncAttributeMaxDynamicSharedMemorySize, SMEM_BYTES);
    cudaFuncSetAttribute(score_k, cudaFuncAttributeMaxDynamicSharedMemorySize, SMEM_BYTES);
    cudaFuncSetAttribute(pv_k,    cudaFuncAttributeMaxDynamicSharedMemorySize, SMEM_BYTES);

    dim3 blk(256);
    splitX_k<<<MTOT * DM / 4 / 256, 256>>>(x);                       // launch 0
    splitW_k<<<3 * NW / 4 / 256, 256>>>(Wq, Wk, Wv);                 // launch 1
    proj_k<<<dim3(8, 64, 3), blk, SMEM_BYTES>>>();                   // launch 2
    score_k<<<dim3(136, 1, NB), blk, SMEM_BYTES>>>();                // launch 3
    softmax_k<<<MTOT, 256>>>(Sb, Ph, Pl);                            // launch 4
    pv_k<<<dim3(DM / BN, SEQ / BM, NB), blk, SMEM_BYTES>>>(out);     // launch 5 (ncu target)
}

// round 9
// speedup vs baseline: 1.6407x; 1.3601x over previous
#include <cuda_runtime.h>
#include <cuda_bf16.h>
#include <cuda_fp16.h>
#include <cstdint>

typedef __nv_bfloat16 bf16;

#define NB   4
#define SEQ  2048
#define DM   1024
#define MTOT (NB*SEQ)          // 8192
#define NW   (DM*DM)

#define BM 128
#define BN 128
#define BK 32
#define STAGES 2
#define TILE_BYTES (BM*BK*2)                // 8192 B per operand tile
#define SMEM3_BYTES (STAGES*4*TILE_BYTES)   // 65536 B (bf16x3: 4 operands)
#define SMEM1_BYTES (STAGES*2*TILE_BYTES)   // 32768 B (fp16x1: 2 operands)

// ------------------------- scratch (__device__ globals; no allocs) ----------
__device__ bf16   g_Xh[MTOT*DM],  g_Xl[MTOT*DM];
__device__ bf16   g_Wqh[NW],      g_Wql[NW];
__device__ bf16   g_Wkh[NW],      g_Wkl[NW];
__device__ bf16   g_Wvh[NW],      g_Wvl[NW];
__device__ __half g_Q16[MTOT*DM];
__device__ __half g_K16[MTOT*DM];
__device__ __half g_V16[DM*MTOT];            // Vt: [DM, MTOT]
__device__ float  g_S[(size_t)MTOT*SEQ];
__device__ __half g_P16[(size_t)MTOT*SEQ];

// ------------------------- PTX helpers -------------------------------------
__device__ __forceinline__ void cp16(void* s, const void* g) {
    uint32_t sa = (uint32_t)__cvta_generic_to_shared(s);
    asm volatile("cp.async.cg.shared.global [%0], [%1], 16;\n" :: "r"(sa), "l"(g));
}
__device__ __forceinline__ void ldsm4(uint32_t* r, const void* p) {
    uint32_t a = (uint32_t)__cvta_generic_to_shared(p);
    asm volatile("ldmatrix.sync.aligned.m8n8.x4.shared.b16 {%0,%1,%2,%3}, [%4];\n"
                 : "=r"(r[0]), "=r"(r[1]), "=r"(r[2]), "=r"(r[3]) : "r"(a));
}
__device__ __forceinline__ void mma_bf16(float* c, const uint32_t* a, const uint32_t* b) {
    asm volatile("mma.sync.aligned.m16n8k16.row.col.f32.bf16.bf16.f32 "
                 "{%0,%1,%2,%3}, {%4,%5,%6,%7}, {%8,%9}, {%0,%1,%2,%3};\n"
                 : "+f"(c[0]), "+f"(c[1]), "+f"(c[2]), "+f"(c[3])
                 : "r"(a[0]), "r"(a[1]), "r"(a[2]), "r"(a[3]), "r"(b[0]), "r"(b[1]));
}
__device__ __forceinline__ void mma_f16(float* c, const uint32_t* a, const uint32_t* b) {
    asm volatile("mma.sync.aligned.m16n8k16.row.col.f32.f16.f16.f32 "
                 "{%0,%1,%2,%3}, {%4,%5,%6,%7}, {%8,%9}, {%0,%1,%2,%3};\n"
                 : "+f"(c[0]), "+f"(c[1]), "+f"(c[2]), "+f"(c[3])
                 : "r"(a[0]), "r"(a[1]), "r"(a[2]), "r"(a[3]), "r"(b[0]), "r"(b[1]));
}
// 16B-chunk XOR swizzle: row stride 64B, chunk' = chunk ^ ((row>>1)&3).
__device__ __forceinline__ int smem_off(int row, int ch) {
    return (row << 6) + (((ch ^ ((row >> 1) & 3)) & 3) << 4);
}

// ------------------------- bf16x3 GEMM core (projections) -------------------
// D[m][n] = sum_k A[m][k]*B[n][k]; epilogue writes fp16
__device__ __forceinline__ void gemm3_core(
    const bf16* __restrict__ Ah, const bf16* __restrict__ Al, int lda,
    const bf16* __restrict__ Bh, const bf16* __restrict__ Bl, int ldb,
    __half* __restrict__ C16, int ldc, int tm, int tn, int kIters, char* smem)
{
    char* sAh = smem;
    char* sAl = smem + 1 * STAGES * TILE_BYTES;
    char* sBh = smem + 2 * STAGES * TILE_BYTES;
    char* sBl = smem + 3 * STAGES * TILE_BYTES;

    const int tid  = threadIdx.x;
    const int lane = tid & 31;
    const int warp = tid >> 5;
    const int wm   = warp >> 2;
    const int wn   = warp & 3;

    auto load_stage = [&](int st, int kOff) {
        char* dAh = sAh + st * TILE_BYTES;
        char* dAl = sAl + st * TILE_BYTES;
        char* dBh = sBh + st * TILE_BYTES;
        char* dBl = sBl + st * TILE_BYTES;
#pragma unroll
        for (int i = 0; i < 2; i++) {
            int idx = tid + (i << 8);
            int row = idx >> 2, ch = idx & 3;
            int so = smem_off(row, ch);
            size_t ga = (size_t)(tm + row) * lda + kOff + (ch << 3);
            size_t gb = (size_t)(tn + row) * ldb + kOff + (ch << 3);
            cp16(dAh + so, Ah + ga);
            cp16(dAl + so, Al + ga);
            cp16(dBh + so, Bh + gb);
            cp16(dBl + so, Bl + gb);
        }
    };

    load_stage(0, 0);
    asm volatile("cp.async.commit_group;\n" ::);

    float acc[4][4][4];
#pragma unroll
    for (int a = 0; a < 4; a++)
#pragma unroll
        for (int b = 0; b < 4; b++)
#pragma unroll
            for (int c = 0; c < 4; c++) acc[a][b][c] = 0.f;

    for (int kb = 0; kb < kIters; kb++) {
        if (kb + 1 < kIters) load_stage((kb + 1) & 1, (kb + 1) * BK);
        asm volatile("cp.async.commit_group;\n" ::);
        asm volatile("cp.async.wait_group 1;\n" ::);
        __syncthreads();

        int st = kb & 1;
        const char* cAh = sAh + st * TILE_BYTES;
        const char* cAl = sAl + st * TILE_BYTES;
        const char* cBh = sBh + st * TILE_BYTES;
        const char* cBl = sBl + st * TILE_BYTES;

#pragma unroll
        for (int ks = 0; ks < 2; ks++) {
            const int k0 = ks * 16;
            uint32_t ah[4][4], al[4][4];
#pragma unroll
            for (int mi = 0; mi < 4; mi++) {
                int r  = wm * 64 + mi * 16 + (lane & 15);
                int ch = (k0 >> 3) + (lane >> 4);
                int so = smem_off(r, ch);
                ldsm4(ah[mi], cAh + so);
                ldsm4(al[mi], cAl + so);
            }
#pragma unroll
            for (int pr = 0; pr < 2; pr++) {
                int n0 = wn * 32 + pr * 16;
                int r  = n0 + (lane & 7) + (((lane >> 4) & 1) << 3);
                int ch = (k0 >> 3) + ((lane >> 3) & 1);
                int so = smem_off(r, ch);
                uint32_t bh[4], bl[4];
                ldsm4(bh, cBh + so);
                ldsm4(bl, cBl + so);
                const int n0i = pr * 2;
#pragma unroll
                for (int mi = 0; mi < 4; mi++) {
                    mma_bf16(acc[mi][n0i + 0], ah[mi], bh + 0);
                    mma_bf16(acc[mi][n0i + 1], ah[mi], bh + 2);
                }
#pragma unroll
                for (int mi = 0; mi < 4; mi++) {
                    mma_bf16(acc[mi][n0i + 0], ah[mi], bl + 0);
                    mma_bf16(acc[mi][n0i + 1], ah[mi], bl + 2);
                }
#pragma unroll
                for (int mi = 0; mi < 4; mi++) {
                    mma_bf16(acc[mi][n0i + 0], al[mi], bh + 0);
                    mma_bf16(acc[mi][n0i + 1], al[mi], bh + 2);
                }
            }
        }
        __syncthreads();
    }

    const int g  = lane >> 2;
    const int tq = lane & 3;
#pragma unroll
    for (int mi = 0; mi < 4; mi++) {
#pragma unroll
        for (int ni = 0; ni < 4; ni++) {
            const float* c = acc[mi][ni];
            int c0 = tn + wn * 32 + ni * 8 + tq * 2;
#pragma unroll
            for (int h = 0; h < 2; h++) {
                int r = tm + wm * 64 + mi * 16 + g + h * 8;
                __half2 hv;
                hv.x = __float2half_rn(c[h * 2 + 0]);
                hv.y = __float2half_rn(c[h * 2 + 1]);
                *(__half2*)&C16[(size_t)r * ldc + c0] = hv;
            }
        }
    }
}

// ------------------------- fp16x1 GEMM core (score / PV) -------------------
// D[m][n] = scale * sum_k A[m][k]*B[n][k]; fp16 operands, fp32 out
__device__ __forceinline__ void gemm1_core(
    const __half* __restrict__ A, int lda,
    const __half* __restrict__ B, int ldb,
    float* __restrict__ Cf, int ldc, int tm, int tn, int kIters,
    float scale, char* smem)
{
    char* sA = smem;
    char* sB = smem + STAGES * TILE_BYTES;

    const int tid  = threadIdx.x;
    const int lane = tid & 31;
    const int warp = tid >> 5;
    const int wm   = warp >> 2;
    const int wn   = warp & 3;

    auto load_stage = [&](int st, int kOff) {
        char* dA = sA + st * TILE_BYTES;
        char* dB = sB + st * TILE_BYTES;
#pragma unroll
        for (int i = 0; i < 2; i++) {
            int idx = tid + (i << 8);
            int row = idx >> 2, ch = idx & 3;
            int so = smem_off(row, ch);
            cp16(dA + so, A + (size_t)(tm + row) * lda + kOff + (ch << 3));
            cp16(dB + so, B + (size_t)(tn + row) * ldb + kOff + (ch << 3));
        }
    };

    load_stage(0, 0);
    asm volatile("cp.async.commit_group;\n" ::);

    float acc[4][4][4];
#pragma unroll
    for (int a = 0; a < 4; a++)
#pragma unroll
        for (int b = 0; b < 4; b++)
#pragma unroll
            for (int c = 0; c < 4; c++) acc[a][b][c] = 0.f;

    for (int kb = 0; kb < kIters; kb++) {
        if (kb + 1 < kIters) load_stage((kb + 1) & 1, (kb + 1) * BK);
        asm volatile("cp.async.commit_group;\n" ::);
        asm volatile("cp.async.wait_group 1;\n" ::);
        __syncthreads();

        int st = kb & 1;
        const char* cA = sA + st * TILE_BYTES;
        const char* cB = sB + st * TILE_BYTES;

#pragma unroll
        for (int ks = 0; ks < 2; ks++) {
            const int k0 = ks * 16;
            uint32_t ah[4][4];
#pragma unroll
            for (int mi = 0; mi < 4; mi++) {
                int r  = wm * 64 + mi * 16 + (lane & 15);
                int ch = (k0 >> 3) + (lane >> 4);
                ldsm4(ah[mi], cA + smem_off(r, ch));
            }
#pragma unroll
            for (int pr = 0; pr < 2; pr++) {
                int n0 = wn * 32 + pr * 16;
                int r  = n0 + (lane & 7) + (((lane >> 4) & 1) << 3);
                int ch = (k0 >> 3) + ((lane >> 3) & 1);
                uint32_t bh[4];
                ldsm4(bh, cB + smem_off(r, ch));
                const int n0i = pr * 2;
#pragma unroll
                for (int mi = 0; mi < 4; mi++) {
                    mma_f16(acc[mi][n0i + 0], ah[mi], bh + 0);
                    mma_f16(acc[mi][n0i + 1], ah[mi], bh + 2);
                }
            }
        }
        __syncthreads();
    }

    const int g  = lane >> 2;
    const int tq = lane & 3;
#pragma unroll
    for (int mi = 0; mi < 4; mi++) {
#pragma unroll
        for (int ni = 0; ni < 4; ni++) {
            const float* c = acc[mi][ni];
            int c0 = tn + wn * 32 + ni * 8 + tq * 2;
#pragma unroll
            for (int h = 0; h < 2; h++) {
                int r = tm + wm * 64 + mi * 16 + g + h * 8;
                float2 o;
                o.x = c[h * 2 + 0] * scale;
                o.y = c[h * 2 + 1] * scale;
                *(float2*)&Cf[(size_t)r * ldc + c0] = o;
            }
        }
    }
}

// ------------------------- GEMM kernels -------------------------------------
// Merged projections: z=0 Q, z=1 K, z=2 Vt (role-swapped tiles)
__global__ void __launch_bounds__(256, 2) proj_k()
{
    extern __shared__ char smem[];
    int z = blockIdx.z;
    if (z == 0) {
        gemm3_core(g_Xh, g_Xl, DM, g_Wqh, g_Wql, DM, g_Q16, DM,
                   blockIdx.y * BM, blockIdx.x * BN, DM / BK, smem);
    } else if (z == 1) {
        gemm3_core(g_Xh, g_Xl, DM, g_Wkh, g_Wkl, DM, g_K16, DM,
                   blockIdx.y * BM, blockIdx.x * BN, DM / BK, smem);
    } else {
        // Vt = Wv @ X^T -> [1024, 8192]; tm over DM (bx<8), tn over MTOT (by<64)
        gemm3_core(g_Wvh, g_Wvl, DM, g_Xh, g_Xl, DM, g_V16, MTOT,
                   blockIdx.x * BM, blockIdx.y * BN, DM / BK, smem);
    }
}

// Causal lower-triangle score tiles: S = (Q K^T)/32  (fp16 operands)
__global__ void __launch_bounds__(256, 2) score_k()
{
    extern __shared__ char smem[];
    int b = blockIdx.z;
    int t = blockIdx.x, ib = 0;
    while ((ib + 1) * (ib + 2) / 2 <= t) ib++;
    int jb = t - ib * (ib + 1) / 2;
    size_t qo = (size_t)b * SEQ * DM;
    gemm1_core(g_Q16 + qo, DM, g_K16 + qo, DM,
               g_S + (size_t)b * SEQ * SEQ, SEQ,
               ib * BM, jb * BN, DM / BK, 0.03125f, smem);
}

// O = P @ V, per-m-tile K limit (fp16 operands)
__global__ void __launch_bounds__(256, 2) pv_k(float* __restrict__ out)
{
    extern __shared__ char smem[];
    int b = blockIdx.z;
    gemm1_core(g_P16 + (size_t)b * SEQ * SEQ, SEQ,
               g_V16 + (size_t)b * SEQ, MTOT,
               out + (size_t)b * SEQ * DM, DM,
               blockIdx.y * BM, blockIdx.x * BN,
               (int)(blockIdx.y + 1) * BM / BK, 1.f, smem);
}

// ------------------------- splits -------------------------------------------
__device__ __forceinline__ void split4(const float* in, bf16* hi, bf16* lo, int i) {
    float4 v = *(const float4*)(in + i);
    bf16 h0 = __float2bfloat16(v.x), h1 = __float2bfloat16(v.y);
    bf16 h2 = __float2bfloat16(v.z), h3 = __float2bfloat16(v.w);
    __nv_bfloat162 a; a.x = h0; a.y = h1;
    __nv_bfloat162 b; b.x = h2; b.y = h3;
    *(__nv_bfloat162*)(hi + i)     = a;
    *(__nv_bfloat162*)(hi + i + 2) = b;
    __nv_bfloat162 c; c.x = __float2bfloat16(v.x - __bfloat162float(h0));
                      c.y = __float2bfloat16(v.y - __bfloat162float(h1));
    __nv_bfloat162 d; d.x = __float2bfloat16(v.z - __bfloat162float(h2));
                      d.y = __float2bfloat16(v.w - __bfloat162float(h3));
    *(__nv_bfloat162*)(lo + i)     = c;
    *(__nv_bfloat162*)(lo + i + 2) = d;
}
__global__ void splitX_k(const float* __restrict__ x) {
    int i = (blockIdx.x * 256 + threadIdx.x) * 4;
    if (i < MTOT * DM) split4(x, g_Xh, g_Xl, i);
}
__global__ void splitW_k(const float* __restrict__ wq,
                         const float* __restrict__ wk,
                         const float* __restrict__ wv) {
    int i = (blockIdx.x * 256 + threadIdx.x) * 4;
    if (i < NW)          split4(wq, g_Wqh, g_Wql, i);
    else if (i < 2 * NW) split4(wk + (i - NW),     g_Wkh + (i - NW),     g_Wkl + (i - NW),     0);
    else if (i < 3 * NW) split4(wv + (i - 2 * NW), g_Wvh + (i - 2 * NW), g_Wvl + (i - 2 * NW), 0);
}

// ------------------------- causal row softmax -> P fp16 ---------------------
__global__ void __launch_bounds__(256) softmax_k(const float* __restrict__ S,
                                                 __half* __restrict__ P16)
{
    __shared__ float buf[SEQ];
    __shared__ float red[8];
    int row = blockIdx.x;
    int b = row >> 11, i = row & 2047;
    int L = i + 1;
    size_t off = ((size_t)b << 22) + ((size_t)i << 11);
    const float* s = S + off;
    int t = threadIdx.x;

    float m = -3.4e38f;
    for (int j = t; j < L; j += 256) { float v = s[j]; buf[j] = v; m = fmaxf(m, v); }
#pragma unroll
    for (int o = 16; o; o >>= 1) m = fmaxf(m, __shfl_xor_sync(0xffffffffu, m, o));
    if ((t & 31) == 0) red[t >> 5] = m;
    __syncthreads();
    float bm = fmaxf(fmaxf(fmaxf(red[0], red[1]), fmaxf(red[2], red[3])),
                     fmaxf(fmaxf(red[4], red[5]), fmaxf(red[6], red[7])));

    float sum = 0.f;
    for (int j = t; j < L; j += 256) { float p = __expf(buf[j] - bm); buf[j] = p; sum += p; }
#pragma unroll
    for (int o = 16; o; o >>= 1) sum += __shfl_xor_sync(0xffffffffu, sum, o);
    __syncthreads();
    if ((t & 31) == 0) red[t >> 5] = sum;
    __syncthreads();
    float tot = red[0] + red[1] + red[2] + red[3] + red[4] + red[5] + red[6] + red[7];
    float inv = 1.f / tot;

    int Lpad = (L + 127) & ~127;   // zero-fill to tile boundary for PV K-limit
    for (int j = t; j < Lpad; j += 256) {
        float v = (j < L) ? buf[j] * inv : 0.f;
        P16[off + j] = __float2half_rn(v);
    }
}

// ------------------------- host orchestration -------------------------------
extern "C" void kernel_launch(void* const* d_in, const int* in_sizes, int n_in,
                              void* d_out, int out_size)
{
    const float* x  = (const float*)d_in[0];
    const float* Wq = (const float*)d_in[1];
    const float* Wk = (const float*)d_in[2];
    const float* Wv = (const float*)d_in[3];
    float* out = (float*)d_out;

    __half* P16;  float* Sb;
    cudaGetSymbolAddress((void**)&P16, g_P16);
    cudaGetSymbolAddress((void**)&Sb,  g_S);

    cudaFuncSetAttribute(proj_k,  cudaFuncAttributeMaxDynamicSharedMemorySize, SMEM3_BYTES);
    cudaFuncSetAttribute(score_k, cudaFuncAttributeMaxDynamicSharedMemorySize, SMEM1_BYTES);
    cudaFuncSetAttribute(pv_k,    cudaFuncAttributeMaxDynamicSharedMemorySize, SMEM1_BYTES);

    dim3 blk(256);
    splitX_k<<<MTOT * DM / 4 / 256, 256>>>(x);                        // launch 0
    splitW_k<<<3 * NW / 4 / 256, 256>>>(Wq, Wk, Wv);                  // launch 1
    proj_k<<<dim3(8, 64, 3), blk, SMEM3_BYTES>>>();                   // launch 2
    score_k<<<dim3(136, 1, NB), blk, SMEM1_BYTES>>>();                // launch 3
    softmax_k<<<MTOT, 256>>>(Sb, P16);                                // launch 4
    pv_k<<<dim3(DM / BN, SEQ / BM, NB), blk, SMEM1_BYTES>>>(out);     // launch 5
}

// round 11
// speedup vs baseline: 2.0986x; 1.2791x over previous
#include <cuda_runtime.h>
#include <cuda_bf16.h>
#include <cuda_fp16.h>
#include <cstdint>

#define NB   4
#define SEQ  2048
#define DM   1024
#define MTOT (NB*SEQ)          // 8192
#define NW   (DM*DM)

#define BM 128
#define BN 128
#define BK 32
#define STAGES 2
#define TILE_BYTES (BM*BK*2)                // 8192 B per operand tile
#define SMEM2_BYTES (STAGES*3*TILE_BYTES)   // 49152 B (fp16 2-term: 3 operands)
#define SMEM1_BYTES (STAGES*2*TILE_BYTES)   // 32768 B (fp16x1: 2 operands)

// ------------------------- scratch (__device__ globals; no allocs) ----------
__device__ __half g_X16h[MTOT*DM], g_X16l[MTOT*DM];
__device__ __half g_Wq16[NW];
__device__ __half g_Wk16[NW];
__device__ __half g_Wv16h[NW],     g_Wv16l[NW];
__device__ __half g_Q16[MTOT*DM];
__device__ __half g_K16[MTOT*DM];
__device__ __half g_V16[DM*MTOT];            // Vt: [DM, MTOT]
__device__ float  g_S[(size_t)MTOT*SEQ];
__device__ __half g_P16[(size_t)MTOT*SEQ];

// ------------------------- PTX helpers -------------------------------------
__device__ __forceinline__ void cp16(void* s, const void* g) {
    uint32_t sa = (uint32_t)__cvta_generic_to_shared(s);
    asm volatile("cp.async.cg.shared.global [%0], [%1], 16;\n" :: "r"(sa), "l"(g));
}
__device__ __forceinline__ void ldsm4(uint32_t* r, const void* p) {
    uint32_t a = (uint32_t)__cvta_generic_to_shared(p);
    asm volatile("ldmatrix.sync.aligned.m8n8.x4.shared.b16 {%0,%1,%2,%3}, [%4];\n"
                 : "=r"(r[0]), "=r"(r[1]), "=r"(r[2]), "=r"(r[3]) : "r"(a));
}
__device__ __forceinline__ void mma_f16(float* c, const uint32_t* a, const uint32_t* b) {
    asm volatile("mma.sync.aligned.m16n8k16.row.col.f32.f16.f16.f32 "
                 "{%0,%1,%2,%3}, {%4,%5,%6,%7}, {%8,%9}, {%0,%1,%2,%3};\n"
                 : "+f"(c[0]), "+f"(c[1]), "+f"(c[2]), "+f"(c[3])
                 : "r"(a[0]), "r"(a[1]), "r"(a[2]), "r"(a[3]), "r"(b[0]), "r"(b[1]));
}
// 16B-chunk XOR swizzle: row stride 64B, chunk' = chunk ^ ((row>>1)&3).
__device__ __forceinline__ int smem_off(int row, int ch) {
    return (row << 6) + (((ch ^ ((row >> 1) & 3)) & 3) << 4);
}

// ------------------------- fp16 2-term GEMM core (projections) --------------
// D[m][n] = sum_k (Ah+Al)[m][k]*B[n][k]; A split fp16 hi/lo, B single fp16.
// Epilogue writes fp16.
__device__ __forceinline__ void gemm2_core(
    const __half* __restrict__ Ah, const __half* __restrict__ Al, int lda,
    const __half* __restrict__ B, int ldb,
    __half* __restrict__ C16, int ldc, int tm, int tn, int kIters, char* smem)
{
    char* sAh = smem;
    char* sAl = smem + 1 * STAGES * TILE_BYTES;
    char* sB  = smem + 2 * STAGES * TILE_BYTES;

    const int tid  = threadIdx.x;
    const int lane = tid & 31;
    const int warp = tid >> 5;
    const int wm   = warp >> 2;
    const int wn   = warp & 3;

    auto load_stage = [&](int st, int kOff) {
        char* dAh = sAh + st * TILE_BYTES;
        char* dAl = sAl + st * TILE_BYTES;
        char* dB  = sB  + st * TILE_BYTES;
#pragma unroll
        for (int i = 0; i < 2; i++) {
            int idx = tid + (i << 8);
            int row = idx >> 2, ch = idx & 3;
            int so = smem_off(row, ch);
            size_t ga = (size_t)(tm + row) * lda + kOff + (ch << 3);
            size_t gb = (size_t)(tn + row) * ldb + kOff + (ch << 3);
            cp16(dAh + so, Ah + ga);
            cp16(dAl + so, Al + ga);
            cp16(dB  + so, B  + gb);
        }
    };

    load_stage(0, 0);
    asm volatile("cp.async.commit_group;\n" ::);

    float acc[4][4][4];
#pragma unroll
    for (int a = 0; a < 4; a++)
#pragma unroll
        for (int b = 0; b < 4; b++)
#pragma unroll
            for (int c = 0; c < 4; c++) acc[a][b][c] = 0.f;

    for (int kb = 0; kb < kIters; kb++) {
        if (kb + 1 < kIters) load_stage((kb + 1) & 1, (kb + 1) * BK);
        asm volatile("cp.async.commit_group;\n" ::);
        asm volatile("cp.async.wait_group 1;\n" ::);
        __syncthreads();

        int st = kb & 1;
        const char* cAh = sAh + st * TILE_BYTES;
        const char* cAl = sAl + st * TILE_BYTES;
        const char* cB  = sB  + st * TILE_BYTES;

#pragma unroll
        for (int ks = 0; ks < 2; ks++) {
            const int k0 = ks * 16;
            uint32_t ah[4][4], al[4][4];
#pragma unroll
            for (int mi = 0; mi < 4; mi++) {
                int r  = wm * 64 + mi * 16 + (lane & 15);
                int ch = (k0 >> 3) + (lane >> 4);
                int so = smem_off(r, ch);
                ldsm4(ah[mi], cAh + so);
                ldsm4(al[mi], cAl + so);
            }
#pragma unroll
            for (int pr = 0; pr < 2; pr++) {
                int n0 = wn * 32 + pr * 16;
                int r  = n0 + (lane & 7) + (((lane >> 4) & 1) << 3);
                int ch = (k0 >> 3) + ((lane >> 3) & 1);
                uint32_t bb[4];
                ldsm4(bb, cB + smem_off(r, ch));
                const int n0i = pr * 2;
                // term-major: 8 independent MMAs per batch
#pragma unroll
                for (int mi = 0; mi < 4; mi++) {
                    mma_f16(acc[mi][n0i + 0], ah[mi], bb + 0);
                    mma_f16(acc[mi][n0i + 1], ah[mi], bb + 2);
                }
#pragma unroll
                for (int mi = 0; mi < 4; mi++) {
                    mma_f16(acc[mi][n0i + 0], al[mi], bb + 0);
                    mma_f16(acc[mi][n0i + 1], al[mi], bb + 2);
                }
            }
        }
        __syncthreads();
    }

    const int g  = lane >> 2;
    const int tq = lane & 3;
#pragma unroll
    for (int mi = 0; mi < 4; mi++) {
#pragma unroll
        for (int ni = 0; ni < 4; ni++) {
            const float* c = acc[mi][ni];
            int c0 = tn + wn * 32 + ni * 8 + tq * 2;
#pragma unroll
            for (int h = 0; h < 2; h++) {
                int r = tm + wm * 64 + mi * 16 + g + h * 8;
                __half2 hv;
                hv.x = __float2half_rn(c[h * 2 + 0]);
                hv.y = __float2half_rn(c[h * 2 + 1]);
                *(__half2*)&C16[(size_t)r * ldc + c0] = hv;
            }
        }
    }
}

// ------------------------- fp16x1 GEMM core (score / PV) -------------------
// D[m][n] = scale * sum_k A[m][k]*B[n][k]; fp16 operands, fp32 out
__device__ __forceinline__ void gemm1_core(
    const __half* __restrict__ A, int lda,
    const __half* __restrict__ B, int ldb,
    float* __restrict__ Cf, int ldc, int tm, int tn, int kIters,
    float scale, char* smem)
{
    char* sA = smem;
    char* sB = smem + STAGES * TILE_BYTES;

    const int tid  = threadIdx.x;
    const int lane = tid & 31;
    const int warp = tid >> 5;
    const int wm   = warp >> 2;
    const int wn   = warp & 3;

    auto load_stage = [&](int st, int kOff) {
        char* dA = sA + st * TILE_BYTES;
        char* dB = sB + st * TILE_BYTES;
#pragma unroll
        for (int i = 0; i < 2; i++) {
            int idx = tid + (i << 8);
            int row = idx >> 2, ch = idx & 3;
            int so = smem_off(row, ch);
            cp16(dA + so, A + (size_t)(tm + row) * lda + kOff + (ch << 3));
            cp16(dB + so, B + (size_t)(tn + row) * ldb + kOff + (ch << 3));
        }
    };

    load_stage(0, 0);
    asm volatile("cp.async.commit_group;\n" ::);

    float acc[4][4][4];
#pragma unroll
    for (int a = 0; a < 4; a++)
#pragma unroll
        for (int b = 0; b < 4; b++)
#pragma unroll
            for (int c = 0; c < 4; c++) acc[a][b][c] = 0.f;

    for (int kb = 0; kb < kIters; kb++) {
        if (kb + 1 < kIters) load_stage((kb + 1) & 1, (kb + 1) * BK);
        asm volatile("cp.async.commit_group;\n" ::);
        asm volatile("cp.async.wait_group 1;\n" ::);
        __syncthreads();

        int st = kb & 1;
        const char* cA = sA + st * TILE_BYTES;
        const char* cB = sB + st * TILE_BYTES;

#pragma unroll
        for (int ks = 0; ks < 2; ks++) {
            const int k0 = ks * 16;
            uint32_t ah[4][4];
#pragma unroll
            for (int mi = 0; mi < 4; mi++) {
                int r  = wm * 64 + mi * 16 + (lane & 15);
                int ch = (k0 >> 3) + (lane >> 4);
                ldsm4(ah[mi], cA + smem_off(r, ch));
            }
#pragma unroll
            for (int pr = 0; pr < 2; pr++) {
                int n0 = wn * 32 + pr * 16;
                int r  = n0 + (lane & 7) + (((lane >> 4) & 1) << 3);
                int ch = (k0 >> 3) + ((lane >> 3) & 1);
                uint32_t bh[4];
                ldsm4(bh, cB + smem_off(r, ch));
                const int n0i = pr * 2;
#pragma unroll
                for (int mi = 0; mi < 4; mi++) {
                    mma_f16(acc[mi][n0i + 0], ah[mi], bh + 0);
                    mma_f16(acc[mi][n0i + 1], ah[mi], bh + 2);
                }
            }
        }
        __syncthreads();
    }

    const int g  = lane >> 2;
    const int tq = lane & 3;
#pragma unroll
    for (int mi = 0; mi < 4; mi++) {
#pragma unroll
        for (int ni = 0; ni < 4; ni++) {
            const float* c = acc[mi][ni];
            int c0 = tn + wn * 32 + ni * 8 + tq * 2;
#pragma unroll
            for (int h = 0; h < 2; h++) {
                int r = tm + wm * 64 + mi * 16 + g + h * 8;
                float2 o;
                o.x = c[h * 2 + 0] * scale;
                o.y = c[h * 2 + 1] * scale;
                *(float2*)&Cf[(size_t)r * ldc + c0] = o;
            }
        }
    }
}

// ------------------------- GEMM kernels -------------------------------------
// Merged projections: z=0 Q, z=1 K, z=2 Vt (role-swapped tiles)
__global__ void __launch_bounds__(256, 2) proj_k()
{
    extern __shared__ char smem[];
    int z = blockIdx.z;
    if (z == 0) {
        gemm2_core(g_X16h, g_X16l, DM, g_Wq16, DM, g_Q16, DM,
                   blockIdx.y * BM, blockIdx.x * BN, DM / BK, smem);
    } else if (z == 1) {
        gemm2_core(g_X16h, g_X16l, DM, g_Wk16, DM, g_K16, DM,
                   blockIdx.y * BM, blockIdx.x * BN, DM / BK, smem);
    } else {
        // Vt = Wv @ X^T -> [1024, 8192]; A = Wv split, B = X (hi = fp16(x))
        gemm2_core(g_Wv16h, g_Wv16l, DM, g_X16h, DM, g_V16, MTOT,
                   blockIdx.x * BM, blockIdx.y * BN, DM / BK, smem);
    }
}

// Causal lower-triangle score tiles: S = (Q K^T)/32  (fp16 operands)
__global__ void __launch_bounds__(256, 2) score_k()
{
    extern __shared__ char smem[];
    int b = blockIdx.z;
    int t = blockIdx.x, ib = 0;
    while ((ib + 1) * (ib + 2) / 2 <= t) ib++;
    int jb = t - ib * (ib + 1) / 2;
    size_t qo = (size_t)b * SEQ * DM;
    gemm1_core(g_Q16 + qo, DM, g_K16 + qo, DM,
               g_S + (size_t)b * SEQ * SEQ, SEQ,
               ib * BM, jb * BN, DM / BK, 0.03125f, smem);
}

// O = P @ V, per-m-tile K limit (fp16 operands)
__global__ void __launch_bounds__(256, 2) pv_k(float* __restrict__ out)
{
    extern __shared__ char smem[];
    int b = blockIdx.z;
    gemm1_core(g_P16 + (size_t)b * SEQ * SEQ, SEQ,
               g_V16 + (size_t)b * SEQ, MTOT,
               out + (size_t)b * SEQ * DM, DM,
               blockIdx.y * BM, blockIdx.x * BN,
               (int)(blockIdx.y + 1) * BM / BK, 1.f, smem);
}

// ------------------------- splits -------------------------------------------
// fp32 -> fp16 hi/lo split (4 elems)
__device__ __forceinline__ void split4h(const float* in, __half* hi, __half* lo, int i) {
    float4 v = *(const float4*)(in + i);
    __half h0 = __float2half_rn(v.x), h1 = __float2half_rn(v.y);
    __half h2 = __float2half_rn(v.z), h3 = __float2half_rn(v.w);
    __half2 a; a.x = h0; a.y = h1;
    __half2 b; b.x = h2; b.y = h3;
    *(__half2*)(hi + i)     = a;
    *(__half2*)(hi + i + 2) = b;
    __half2 c; c.x = __float2half_rn(v.x - __half2float(h0));
               c.y = __float2half_rn(v.y - __half2float(h1));
    __half2 d; d.x = __float2half_rn(v.z - __half2float(h2));
               d.y = __float2half_rn(v.w - __half2float(h3));
    *(__half2*)(lo + i)     = c;
    *(__half2*)(lo + i + 2) = d;
}
// fp32 -> fp16 single (4 elems)
__device__ __forceinline__ void conv4h(const float* in, __half* out, int i) {
    float4 v = *(const float4*)(in + i);
    __half2 a; a.x = __float2half_rn(v.x); a.y = __float2half_rn(v.y);
    __half2 b; b.x = __float2half_rn(v.z); b.y = __float2half_rn(v.w);
    *(__half2*)(out + i)     = a;
    *(__half2*)(out + i + 2) = b;
}
__global__ void splitX_k(const float* __restrict__ x) {
    int i = (blockIdx.x * 256 + threadIdx.x) * 4;
    if (i < MTOT * DM) split4h(x, g_X16h, g_X16l, i);
}
__global__ void splitW_k(const float* __restrict__ wq,
                         const float* __restrict__ wk,
                         const float* __restrict__ wv) {
    int i = (blockIdx.x * 256 + threadIdx.x) * 4;
    if (i < NW)          conv4h(wq, g_Wq16, i);
    else if (i < 2 * NW) conv4h(wk + (i - NW), g_Wk16 + (i - NW), 0);
    else if (i < 3 * NW) split4h(wv + (i - 2 * NW), g_Wv16h + (i - 2 * NW),
                                 g_Wv16l + (i - 2 * NW), 0);
}

// ------------------------- causal row softmax -> P fp16 ---------------------
__global__ void __launch_bounds__(256) softmax_k(const float* __restrict__ S,
                                                 __half* __restrict__ P16)
{
    __shared__ float buf[SEQ];
    __shared__ float red[8];
    int row = blockIdx.x;
    int b = row >> 11, i = row & 2047;
    int L = i + 1;
    size_t off = ((size_t)b << 22) + ((size_t)i << 11);
    const float* s = S + off;
    int t = threadIdx.x;

    float m = -3.4e38f;
    for (int j = t; j < L; j += 256) { float v = s[j]; buf[j] = v; m = fmaxf(m, v); }
#pragma unroll
    for (int o = 16; o; o >>= 1) m = fmaxf(m, __shfl_xor_sync(0xffffffffu, m, o));
    if ((t & 31) == 0) red[t >> 5] = m;
    __syncthreads();
    float bm = fmaxf(fmaxf(fmaxf(red[0], red[1]), fmaxf(red[2], red[3])),
                     fmaxf(fmaxf(red[4], red[5]), fmaxf(red[6], red[7])));

    float sum = 0.f;
    for (int j = t; j < L; j += 256) { float p = __expf(buf[j] - bm); buf[j] = p; sum += p; }
#pragma unroll
    for (int o = 16; o; o >>= 1) sum += __shfl_xor_sync(0xffffffffu, sum, o);
    __syncthreads();
    if ((t & 31) == 0) red[t >> 5] = sum;
    __syncthreads();
    float tot = red[0] + red[1] + red[2] + red[3] + red[4] + red[5] + red[6] + red[7];
    float inv = 1.f / tot;

    int Lpad = (L + 127) & ~127;   // zero-fill to tile boundary for PV K-limit
    for (int j = t; j < Lpad; j += 256) {
        float v = (j < L) ? buf[j] * inv : 0.f;
        P16[off + j] = __float2half_rn(v);
    }
}

// ------------------------- host orchestration -------------------------------
extern "C" void kernel_launch(void* const* d_in, const int* in_sizes, int n_in,
                              void* d_out, int out_size)
{
    const float* x  = (const float*)d_in[0];
    const float* Wq = (const float*)d_in[1];
    const float* Wk = (const float*)d_in[2];
    const float* Wv = (const float*)d_in[3];
    float* out = (float*)d_out;

    __half* P16;  float* Sb;
    cudaGetSymbolAddress((void**)&P16, g_P16);
    cudaGetSymbolAddress((void**)&Sb,  g_S);

    cudaFuncSetAttribute(proj_k,  cudaFuncAttributeMaxDynamicSharedMemorySize, SMEM2_BYTES);
    cudaFuncSetAttribute(score_k, cudaFuncAttributeMaxDynamicSharedMemorySize, SMEM1_BYTES);
    cudaFuncSetAttribute(pv_k,    cudaFuncAttributeMaxDynamicSharedMemorySize, SMEM1_BYTES);

    dim3 blk(256);
    splitX_k<<<MTOT * DM / 4 / 256, 256>>>(x);                        // launch 0
    splitW_k<<<3 * NW / 4 / 256, 256>>>(Wq, Wk, Wv);                  // launch 1
    proj_k<<<dim3(8, 64, 3), blk, SMEM2_BYTES>>>();                   // launch 2
    score_k<<<dim3(136, 1, NB), blk, SMEM1_BYTES>>>();                // launch 3
    softmax_k<<<MTOT, 256>>>(Sb, P16);                                // launch 4
    pv_k<<<dim3(DM / BN, SEQ / BM, NB), blk, SMEM1_BYTES>>>(out);     // launch 5
}

// round 12
// speedup vs baseline: 2.8293x; 1.3482x over previous
#include <cuda_runtime.h>
#include <cuda_fp16.h>
#include <cstdint>

#define NB   4
#define SEQ  2048
#define DM   1024
#define MTOT (NB*SEQ)          // 8192
#define NW   (DM*DM)

#define BM 128
#define BN 128
#define BK 32
#define STAGES 3
#define TILE_BYTES (BM*BK*2)                // 8192 B per operand tile
#define SMEM_BYTES (STAGES*2*TILE_BYTES)    // 49152 B -> 2 CTAs/SM

// ------------------------- scratch (__device__ globals; no allocs) ----------
__device__ __half g_X16[MTOT*DM];
__device__ __half g_Wq16[NW];
__device__ __half g_Wk16[NW];
__device__ __half g_Wv16[NW];
__device__ __half g_Q16[MTOT*DM];
__device__ __half g_K16[MTOT*DM];
__device__ __half g_V16[DM*MTOT];            // Vt: [DM, MTOT]
__device__ float  g_S[(size_t)MTOT*SEQ];
__device__ __half g_P16[(size_t)MTOT*SEQ];

// ------------------------- PTX helpers -------------------------------------
__device__ __forceinline__ void cp16(void* s, const void* g) {
    uint32_t sa = (uint32_t)__cvta_generic_to_shared(s);
    asm volatile("cp.async.cg.shared.global [%0], [%1], 16;\n" :: "r"(sa), "l"(g));
}
__device__ __forceinline__ void ldsm4(uint32_t* r, const void* p) {
    uint32_t a = (uint32_t)__cvta_generic_to_shared(p);
    asm volatile("ldmatrix.sync.aligned.m8n8.x4.shared.b16 {%0,%1,%2,%3}, [%4];\n"
                 : "=r"(r[0]), "=r"(r[1]), "=r"(r[2]), "=r"(r[3]) : "r"(a));
}
__device__ __forceinline__ void mma_f16(float* c, const uint32_t* a, const uint32_t* b) {
    asm volatile("mma.sync.aligned.m16n8k16.row.col.f32.f16.f16.f32 "
                 "{%0,%1,%2,%3}, {%4,%5,%6,%7}, {%8,%9}, {%0,%1,%2,%3};\n"
                 : "+f"(c[0]), "+f"(c[1]), "+f"(c[2]), "+f"(c[3])
                 : "r"(a[0]), "r"(a[1]), "r"(a[2]), "r"(a[3]), "r"(b[0]), "r"(b[1]));
}
// 16B-chunk XOR swizzle: row stride 64B, chunk' = chunk ^ ((row>>1)&3).
__device__ __forceinline__ int smem_off(int row, int ch) {
    return (row << 6) + (((ch ^ ((row >> 1) & 3)) & 3) << 4);
}

// ------------------------- fp16 single-pass GEMM core -----------------------
// D[m][n] = scale * sum_k A[m][k]*B[n][k]  (both K-major fp16)
// OUT 0: fp16 output    OUT 1: fp32 * scale
template<int OUT>
__device__ __forceinline__ void gemm_core(
    const __half* __restrict__ A, int lda,
    const __half* __restrict__ B, int ldb,
    float* __restrict__ Cf, __half* __restrict__ C16, int ldc,
    int tm, int tn, int kIters, float scale, char* smem)
{
    char* sA = smem;
    char* sB = smem + STAGES * TILE_BYTES;

    const int tid  = threadIdx.x;
    const int lane = tid & 31;
    const int warp = tid >> 5;
    const int wm   = warp >> 2;   // 0..1 (64 rows each)
    const int wn   = warp & 3;    // 0..3 (32 cols each)

    auto load_stage = [&](int st, int kOff) {
        char* dA = sA + st * TILE_BYTES;
        char* dB = sB + st * TILE_BYTES;
#pragma unroll
        for (int i = 0; i < 2; i++) {
            int idx = tid + (i << 8);
            int row = idx >> 2, ch = idx & 3;
            int so = smem_off(row, ch);
            cp16(dA + so, A + (size_t)(tm + row) * lda + kOff + (ch << 3));
            cp16(dB + so, B + (size_t)(tn + row) * ldb + kOff + (ch << 3));
        }
    };

    // prologue: prefetch depth 2
#pragma unroll
    for (int s = 0; s < STAGES - 1; s++) {
        if (s < kIters) load_stage(s, s * BK);
        asm volatile("cp.async.commit_group;\n" ::);
    }

    float acc[4][4][4];
#pragma unroll
    for (int a = 0; a < 4; a++)
#pragma unroll
        for (int b = 0; b < 4; b++)
#pragma unroll
            for (int c = 0; c < 4; c++) acc[a][b][c] = 0.f;

    for (int kb = 0; kb < kIters; kb++) {
        asm volatile("cp.async.wait_group 1;\n" ::);   // stage kb resident
        __syncthreads();
        int nk = kb + STAGES - 1;
        if (nk < kIters) load_stage(nk % STAGES, nk * BK);
        asm volatile("cp.async.commit_group;\n" ::);

        int st = kb % STAGES;
        const char* cA = sA + st * TILE_BYTES;
        const char* cB = sB + st * TILE_BYTES;

#pragma unroll
        for (int ks = 0; ks < 2; ks++) {
            const int k0 = ks * 16;
            uint32_t ah[4][4];
#pragma unroll
            for (int mi = 0; mi < 4; mi++) {
                int r  = wm * 64 + mi * 16 + (lane & 15);
                int ch = (k0 >> 3) + (lane >> 4);
                ldsm4(ah[mi], cA + smem_off(r, ch));
            }
#pragma unroll
            for (int pr = 0; pr < 2; pr++) {
                int n0 = wn * 32 + pr * 16;
                int r  = n0 + (lane & 7) + (((lane >> 4) & 1) << 3);
                int ch = (k0 >> 3) + ((lane >> 3) & 1);
                uint32_t bh[4];
                ldsm4(bh, cB + smem_off(r, ch));
                const int n0i = pr * 2;
#pragma unroll
                for (int mi = 0; mi < 4; mi++) {
                    mma_f16(acc[mi][n0i + 0], ah[mi], bh + 0);
                    mma_f16(acc[mi][n0i + 1], ah[mi], bh + 2);
                }
            }
        }
        __syncthreads();
    }

    const int g  = lane >> 2;
    const int tq = lane & 3;
#pragma unroll
    for (int mi = 0; mi < 4; mi++) {
#pragma unroll
        for (int ni = 0; ni < 4; ni++) {
            const float* c = acc[mi][ni];
            int c0 = tn + wn * 32 + ni * 8 + tq * 2;
#pragma unroll
            for (int h = 0; h < 2; h++) {
                int r = tm + wm * 64 + mi * 16 + g + h * 8;
                if (OUT == 0) {
                    __half2 hv;
                    hv.x = __float2half_rn(c[h * 2 + 0]);
                    hv.y = __float2half_rn(c[h * 2 + 1]);
                    *(__half2*)&C16[(size_t)r * ldc + c0] = hv;
                } else {
                    float2 o;
                    o.x = c[h * 2 + 0] * scale;
                    o.y = c[h * 2 + 1] * scale;
                    *(float2*)&Cf[(size_t)r * ldc + c0] = o;
                }
            }
        }
    }
}

// ------------------------- GEMM kernels -------------------------------------
// Merged projections: z=0 Q, z=1 K, z=2 Vt (role-swapped tiles)
__global__ void __launch_bounds__(256, 2) proj_k()
{
    extern __shared__ char smem[];
    int z = blockIdx.z;
    if (z == 0) {
        gemm_core<0>(g_X16, DM, g_Wq16, DM, nullptr, g_Q16, DM,
                     blockIdx.y * BM, blockIdx.x * BN, DM / BK, 1.f, smem);
    } else if (z == 1) {
        gemm_core<0>(g_X16, DM, g_Wk16, DM, nullptr, g_K16, DM,
                     blockIdx.y * BM, blockIdx.x * BN, DM / BK, 1.f, smem);
    } else {
        // Vt = Wv @ X^T -> [1024, 8192]; tm over DM (bx<8), tn over MTOT (by<64)
        gemm_core<0>(g_Wv16, DM, g_X16, DM, nullptr, g_V16, MTOT,
                     blockIdx.x * BM, blockIdx.y * BN, DM / BK, 1.f, smem);
    }
}

// Causal lower-triangle score tiles: S = (Q K^T)/32
__global__ void __launch_bounds__(256, 2) score_k()
{
    extern __shared__ char smem[];
    int b = blockIdx.z;
    int t = blockIdx.x, ib = 0;
    while ((ib + 1) * (ib + 2) / 2 <= t) ib++;
    int jb = t - ib * (ib + 1) / 2;
    size_t qo = (size_t)b * SEQ * DM;
    gemm_core<1>(g_Q16 + qo, DM, g_K16 + qo, DM,
                 g_S + (size_t)b * SEQ * SEQ, nullptr, SEQ,
                 ib * BM, jb * BN, DM / BK, 0.03125f, smem);
}

// O = P @ V, per-m-tile K limit
__global__ void __launch_bounds__(256, 2) pv_k(float* __restrict__ out)
{
    extern __shared__ char smem[];
    int b = blockIdx.z;
    gemm_core<1>(g_P16 + (size_t)b * SEQ * SEQ, SEQ,
                 g_V16 + (size_t)b * SEQ, MTOT,
                 out + (size_t)b * SEQ * DM, nullptr, DM,
                 blockIdx.y * BM, blockIdx.x * BN,
                 (int)(blockIdx.y + 1) * BM / BK, 1.f, smem);
}

// ------------------------- converts -----------------------------------------
// fp32 -> fp16 (4 elems)
__device__ __forceinline__ void conv4h(const float* in, __half* out, int i) {
    float4 v = *(const float4*)(in + i);
    __half2 a; a.x = __float2half_rn(v.x); a.y = __float2half_rn(v.y);
    __half2 b; b.x = __float2half_rn(v.z); b.y = __float2half_rn(v.w);
    *(__half2*)(out + i)     = a;
    *(__half2*)(out + i + 2) = b;
}
__global__ void convX_k(const float* __restrict__ x) {
    int i = (blockIdx.x * 256 + threadIdx.x) * 4;
    if (i < MTOT * DM) conv4h(x, g_X16, i);
}
__global__ void convW_k(const float* __restrict__ wq,
                        const float* __restrict__ wk,
                        const float* __restrict__ wv) {
    int i = (blockIdx.x * 256 + threadIdx.x) * 4;
    if (i < NW)          conv4h(wq, g_Wq16, i);
    else if (i < 2 * NW) conv4h(wk + (i - NW),     g_Wk16 + (i - NW),     0);
    else if (i < 3 * NW) conv4h(wv + (i - 2 * NW), g_Wv16 + (i - 2 * NW), 0);
}

// ------------------------- causal row softmax -> P fp16 ---------------------
__global__ void __launch_bounds__(256) softmax_k(const float* __restrict__ S,
                                                 __half* __restrict__ P16)
{
    __shared__ float buf[SEQ];
    __shared__ float red[8];
    int row = blockIdx.x;
    int b = row >> 11, i = row & 2047;
    int L = i + 1;
    size_t off = ((size_t)b << 22) + ((size_t)i << 11);
    const float* s = S + off;
    int t = threadIdx.x;

    float m = -3.4e38f;
    for (int j = t; j < L; j += 256) { float v = s[j]; buf[j] = v; m = fmaxf(m, v); }
#pragma unroll
    for (int o = 16; o; o >>= 1) m = fmaxf(m, __shfl_xor_sync(0xffffffffu, m, o));
    if ((t & 31) == 0) red[t >> 5] = m;
    __syncthreads();
    float bm = fmaxf(fmaxf(fmaxf(red[0], red[1]), fmaxf(red[2], red[3])),
                     fmaxf(fmaxf(red[4], red[5]), fmaxf(red[6], red[7])));

    float sum = 0.f;
    for (int j = t; j < L; j += 256) { float p = __expf(buf[j] - bm); buf[j] = p; sum += p; }
#pragma unroll
    for (int o = 16; o; o >>= 1) sum += __shfl_xor_sync(0xffffffffu, sum, o);
    __syncthreads();
    if ((t & 31) == 0) red[t >> 5] = sum;
    __syncthreads();
    float tot = red[0] + red[1] + red[2] + red[3] + red[4] + red[5] + red[6] + red[7];
    float inv = 1.f / tot;

    int Lpad = (L + 127) & ~127;   // zero-fill to tile boundary for PV K-limit
    for (int j = t; j < Lpad; j += 256) {
        float v = (j < L) ? buf[j] * inv : 0.f;
        P16[off + j] = __float2half_rn(v);
    }
}

// ------------------------- host orchestration -------------------------------
extern "C" void kernel_launch(void* const* d_in, const int* in_sizes, int n_in,
                              void* d_out, int out_size)
{
    const float* x  = (const float*)d_in[0];
    const float* Wq = (const float*)d_in[1];
    const float* Wk = (const float*)d_in[2];
    const float* Wv = (const float*)d_in[3];
    float* out = (float*)d_out;

    __half* P16;  float* Sb;
    cudaGetSymbolAddress((void**)&P16, g_P16);
    cudaGetSymbolAddress((void**)&Sb,  g_S);

    cudaFuncSetAttribute(proj_k,  cudaFuncAttributeMaxDynamicSharedMemorySize, SMEM_BYTES);
    cudaFuncSetAttribute(score_k, cudaFuncAttributeMaxDynamicSharedMemorySize, SMEM_BYTES);
    cudaFuncSetAttribute(pv_k,    cudaFuncAttributeMaxDynamicSharedMemorySize, SMEM_BYTES);

    dim3 blk(256);
    convX_k<<<MTOT * DM / 4 / 256, 256>>>(x);                        // launch 0
    convW_k<<<3 * NW / 4 / 256, 256>>>(Wq, Wk, Wv);                  // launch 1
    proj_k<<<dim3(8, 64, 3), blk, SMEM_BYTES>>>();                   // launch 2
    score_k<<<dim3(136, 1, NB), blk, SMEM_BYTES>>>();                // launch 3
    softmax_k<<<MTOT, 256>>>(Sb, P16);                               // launch 4
    pv_k<<<dim3(DM / BN, SEQ / BM, NB), blk, SMEM_BYTES>>>(out);     // launch 5
}

// round 13
// speedup vs baseline: 3.0689x; 1.0847x over previous
#include <cuda_runtime.h>
#include <cuda_fp16.h>
#include <cstdint>

#define NB   4
#define SEQ  2048
#define DM   1024
#define MTOT (NB*SEQ)          // 8192
#define NW   (DM*DM)

#define BM 128
#define BN 128
#define BK 64
#define STAGES 3
#define TILE_BYTES (BM*BK*2)                // 16384 B per operand tile (128B rows)
#define SMEM_BYTES (STAGES*2*TILE_BYTES)    // 98304 B -> 2 CTAs/SM (192KB/228KB)

// ------------------------- scratch (__device__ globals; no allocs) ----------
__device__ __half g_X16[MTOT*DM];
__device__ __half g_Wq16[NW];
__device__ __half g_Wk16[NW];
__device__ __half g_Wv16[NW];
__device__ __half g_Q16[MTOT*DM];
__device__ __half g_K16[MTOT*DM];
__device__ __half g_V16[DM*MTOT];            // Vt: [DM, MTOT]
__device__ float  g_S[(size_t)MTOT*SEQ];
__device__ __half g_P16[(size_t)MTOT*SEQ];

// ------------------------- PTX helpers -------------------------------------
__device__ __forceinline__ void cp16(void* s, const void* g) {
    uint32_t sa = (uint32_t)__cvta_generic_to_shared(s);
    asm volatile("cp.async.cg.shared.global [%0], [%1], 16;\n" :: "r"(sa), "l"(g));
}
__device__ __forceinline__ void ldsm4(uint32_t* r, const void* p) {
    uint32_t a = (uint32_t)__cvta_generic_to_shared(p);
    asm volatile("ldmatrix.sync.aligned.m8n8.x4.shared.b16 {%0,%1,%2,%3}, [%4];\n"
                 : "=r"(r[0]), "=r"(r[1]), "=r"(r[2]), "=r"(r[3]) : "r"(a));
}
__device__ __forceinline__ void mma_f16(float* c, const uint32_t* a, const uint32_t* b) {
    asm volatile("mma.sync.aligned.m16n8k16.row.col.f32.f16.f16.f32 "
                 "{%0,%1,%2,%3}, {%4,%5,%6,%7}, {%8,%9}, {%0,%1,%2,%3};\n"
                 : "+f"(c[0]), "+f"(c[1]), "+f"(c[2]), "+f"(c[3])
                 : "r"(a[0]), "r"(a[1]), "r"(a[2]), "r"(a[3]), "r"(b[0]), "r"(b[1]));
}
// 128B rows, 8x16B chunks; chunk' = ch ^ (row&7).
// ldmatrix: 8 rows at fixed ch -> 8 distinct 16B slots (conflict-free).
// cp.async: 8 lanes cover one row's 128B (conflict-free).
__device__ __forceinline__ int smem_off(int row, int ch) {
    return (row << 7) + (((ch ^ (row & 7)) & 7) << 4);
}

// ------------------------- fp16 single-pass GEMM core -----------------------
// D[m][n] = scale * sum_k A[m][k]*B[n][k]  (both K-major fp16)
// OUT 0: fp16 output    OUT 1: fp32 * scale
template<int OUT>
__device__ __forceinline__ void gemm_core(
    const __half* __restrict__ A, int lda,
    const __half* __restrict__ B, int ldb,
    float* __restrict__ Cf, __half* __restrict__ C16, int ldc,
    int tm, int tn, int kIters, float scale, char* smem)
{
    char* sA = smem;
    char* sB = smem + STAGES * TILE_BYTES;

    const int tid  = threadIdx.x;
    const int lane = tid & 31;
    const int warp = tid >> 5;
    const int wm   = warp >> 2;   // 0..1 (64 rows each)
    const int wn   = warp & 3;    // 0..3 (32 cols each)

    auto load_stage = [&](int st, int kOff) {
        char* dA = sA + st * TILE_BYTES;
        char* dB = sB + st * TILE_BYTES;
#pragma unroll
        for (int i = 0; i < 4; i++) {
            int idx = tid + (i << 8);
            int row = idx >> 3, ch = idx & 7;
            int so = smem_off(row, ch);
            cp16(dA + so, A + (size_t)(tm + row) * lda + kOff + (ch << 3));
            cp16(dB + so, B + (size_t)(tn + row) * ldb + kOff + (ch << 3));
        }
    };

    // prologue: prefetch depth 2
#pragma unroll
    for (int s = 0; s < STAGES - 1; s++) {
        if (s < kIters) load_stage(s, s * BK);
        asm volatile("cp.async.commit_group;\n" ::);
    }

    float acc[4][4][4];
#pragma unroll
    for (int a = 0; a < 4; a++)
#pragma unroll
        for (int b = 0; b < 4; b++)
#pragma unroll
            for (int c = 0; c < 4; c++) acc[a][b][c] = 0.f;

    for (int kb = 0; kb < kIters; kb++) {
        asm volatile("cp.async.wait_group 1;\n" ::);   // stage kb resident
        __syncthreads();                                // single sync per iter
        int nk = kb + STAGES - 1;
        if (nk < kIters) load_stage(nk % STAGES, nk * BK);
        asm volatile("cp.async.commit_group;\n" ::);

        int st = kb % STAGES;
        const char* cA = sA + st * TILE_BYTES;
        const char* cB = sB + st * TILE_BYTES;

#pragma unroll
        for (int ks = 0; ks < 4; ks++) {
            uint32_t ah[4][4];
#pragma unroll
            for (int mi = 0; mi < 4; mi++) {
                int r  = wm * 64 + mi * 16 + (lane & 15);
                int ch = ks * 2 + (lane >> 4);
                ldsm4(ah[mi], cA + smem_off(r, ch));
            }
#pragma unroll
            for (int pr = 0; pr < 2; pr++) {
                int r  = wn * 32 + pr * 16 + (lane & 7) + (((lane >> 4) & 1) << 3);
                int ch = ks * 2 + ((lane >> 3) & 1);
                uint32_t bh[4];
                ldsm4(bh, cB + smem_off(r, ch));
                const int n0i = pr * 2;
#pragma unroll
                for (int mi = 0; mi < 4; mi++) {
                    mma_f16(acc[mi][n0i + 0], ah[mi], bh + 0);
                    mma_f16(acc[mi][n0i + 1], ah[mi], bh + 2);
                }
            }
        }
    }

    __syncthreads();   // protect last-read stages before (hypothetical) reuse; also
                       // separates mainloop smem use from epilogue (cheap, once)

    const int g  = lane >> 2;
    const int tq = lane & 3;
#pragma unroll
    for (int mi = 0; mi < 4; mi++) {
#pragma unroll
        for (int ni = 0; ni < 4; ni++) {
            const float* c = acc[mi][ni];
            int c0 = tn + wn * 32 + ni * 8 + tq * 2;
#pragma unroll
            for (int h = 0; h < 2; h++) {
                int r = tm + wm * 64 + mi * 16 + g + h * 8;
                if (OUT == 0) {
                    __half2 hv;
                    hv.x = __float2half_rn(c[h * 2 + 0]);
                    hv.y = __float2half_rn(c[h * 2 + 1]);
                    *(__half2*)&C16[(size_t)r * ldc + c0] = hv;
                } else {
                    float2 o;
                    o.x = c[h * 2 + 0] * scale;
                    o.y = c[h * 2 + 1] * scale;
                    *(float2*)&Cf[(size_t)r * ldc + c0] = o;
                }
            }
        }
    }
}

// ------------------------- GEMM kernels -------------------------------------
// Merged projections: z=0 Q, z=1 K, z=2 Vt (role-swapped tiles)
__global__ void __launch_bounds__(256, 2) proj_k()
{
    extern __shared__ char smem[];
    int z = blockIdx.z;
    if (z == 0) {
        gemm_core<0>(g_X16, DM, g_Wq16, DM, nullptr, g_Q16, DM,
                     blockIdx.y * BM, blockIdx.x * BN, DM / BK, 1.f, smem);
    } else if (z == 1) {
        gemm_core<0>(g_X16, DM, g_Wk16, DM, nullptr, g_K16, DM,
                     blockIdx.y * BM, blockIdx.x * BN, DM / BK, 1.f, smem);
    } else {
        // Vt = Wv @ X^T -> [1024, 8192]; tm over DM (bx<8), tn over MTOT (by<64)
        gemm_core<0>(g_Wv16, DM, g_X16, DM, nullptr, g_V16, MTOT,
                     blockIdx.x * BM, blockIdx.y * BN, DM / BK, 1.f, smem);
    }
}

// Causal lower-triangle score tiles: S = (Q K^T)/32
__global__ void __launch_bounds__(256, 2) score_k()
{
    extern __shared__ char smem[];
    int b = blockIdx.z;
    int t = blockIdx.x, ib = 0;
    while ((ib + 1) * (ib + 2) / 2 <= t) ib++;
    int jb = t - ib * (ib + 1) / 2;
    size_t qo = (size_t)b * SEQ * DM;
    gemm_core<1>(g_Q16 + qo, DM, g_K16 + qo, DM,
                 g_S + (size_t)b * SEQ * SEQ, nullptr, SEQ,
                 ib * BM, jb * BN, DM / BK, 0.03125f, smem);
}

// O = P @ V, per-m-tile K limit: (by+1)*128 cols = (by+1)*2 BK-iters
__global__ void __launch_bounds__(256, 2) pv_k(float* __restrict__ out)
{
    extern __shared__ char smem[];
    int b = blockIdx.z;
    gemm_core<1>(g_P16 + (size_t)b * SEQ * SEQ, SEQ,
                 g_V16 + (size_t)b * SEQ, MTOT,
                 out + (size_t)b * SEQ * DM, nullptr, DM,
                 blockIdx.y * BM, blockIdx.x * BN,
                 (int)(blockIdx.y + 1) * BM / BK, 1.f, smem);
}

// ------------------------- converts -----------------------------------------
// fp32 -> fp16 (4 elems)
__device__ __forceinline__ void conv4h(const float* in, __half* out, int i) {
    float4 v = *(const float4*)(in + i);
    __half2 a; a.x = __float2half_rn(v.x); a.y = __float2half_rn(v.y);
    __half2 b; b.x = __float2half_rn(v.z); b.y = __float2half_rn(v.w);
    *(__half2*)(out + i)     = a;
    *(__half2*)(out + i + 2) = b;
}
__global__ void convX_k(const float* __restrict__ x) {
    int i = (blockIdx.x * 256 + threadIdx.x) * 4;
    if (i < MTOT * DM) conv4h(x, g_X16, i);
}
__global__ void convW_k(const float* __restrict__ wq,
                        const float* __restrict__ wk,
                        const float* __restrict__ wv) {
    int i = (blockIdx.x * 256 + threadIdx.x) * 4;
    if (i < NW)          conv4h(wq, g_Wq16, i);
    else if (i < 2 * NW) conv4h(wk + (i - NW),     g_Wk16 + (i - NW),     0);
    else if (i < 3 * NW) conv4h(wv + (i - 2 * NW), g_Wv16 + (i - 2 * NW), 0);
}

// ------------------------- causal row softmax -> P fp16 ---------------------
__global__ void __launch_bounds__(256) softmax_k(const float* __restrict__ S,
                                                 __half* __restrict__ P16)
{
    __shared__ float buf[SEQ];
    __shared__ float red[8];
    int row = blockIdx.x;
    int b = row >> 11, i = row & 2047;
    int L = i + 1;
    size_t off = ((size_t)b << 22) + ((size_t)i << 11);
    const float* s = S + off;
    int t = threadIdx.x;

    float m = -3.4e38f;
    for (int j = t; j < L; j += 256) { float v = s[j]; buf[j] = v; m = fmaxf(m, v); }
#pragma unroll
    for (int o = 16; o; o >>= 1) m = fmaxf(m, __shfl_xor_sync(0xffffffffu, m, o));
    if ((t & 31) == 0) red[t >> 5] = m;
    __syncthreads();
    float bm = fmaxf(fmaxf(fmaxf(red[0], red[1]), fmaxf(red[2], red[3])),
                     fmaxf(fmaxf(red[4], red[5]), fmaxf(red[6], red[7])));

    float sum = 0.f;
    for (int j = t; j < L; j += 256) { float p = __expf(buf[j] - bm); buf[j] = p; sum += p; }
#pragma unroll
    for (int o = 16; o; o >>= 1) sum += __shfl_xor_sync(0xffffffffu, sum, o);
    __syncthreads();
    if ((t & 31) == 0) red[t >> 5] = sum;
    __syncthreads();
    float tot = red[0] + red[1] + red[2] + red[3] + red[4] + red[5] + red[6] + red[7];
    float inv = 1.f / tot;

    int Lpad = (L + 127) & ~127;   // zero-fill to tile boundary for PV K-limit
    for (int j = t; j < Lpad; j += 256) {
        float v = (j < L) ? buf[j] * inv : 0.f;
        P16[off + j] = __float2half_rn(v);
    }
}

// ------------------------- host orchestration -------------------------------
extern "C" void kernel_launch(void* const* d_in, const int* in_sizes, int n_in,
                              void* d_out, int out_size)
{
    const float* x  = (const float*)d_in[0];
    const float* Wq = (const float*)d_in[1];
    const float* Wk = (const float*)d_in[2];
    const float* Wv = (const float*)d_in[3];
    float* out = (float*)d_out;

    __half* P16;  float* Sb;
    cudaGetSymbolAddress((void**)&P16, g_P16);
    cudaGetSymbolAddress((void**)&Sb,  g_S);

    cudaFuncSetAttribute(proj_k,  cudaFuncAttributeMaxDynamicSharedMemorySize, SMEM_BYTES);
    cudaFuncSetAttribute(score_k, cudaFuncAttributeMaxDynamicSharedMemorySize, SMEM_BYTES);
    cudaFuncSetAttribute(pv_k,    cudaFuncAttributeMaxDynamicSharedMemorySize, SMEM_BYTES);

    dim3 blk(256);
    convX_k<<<MTOT * DM / 4 / 256, 256>>>(x);                        // launch 0
    convW_k<<<3 * NW / 4 / 256, 256>>>(Wq, Wk, Wv);                  // launch 1
    proj_k<<<dim3(8, 64, 3), blk, SMEM_BYTES>>>();                   // launch 2
    score_k<<<dim3(136, 1, NB), blk, SMEM_BYTES>>>();                // launch 3
    softmax_k<<<MTOT, 256>>>(Sb, P16);                               // launch 4
    pv_k<<<dim3(DM / BN, SEQ / BM, NB), blk, SMEM_BYTES>>>(out);     // launch 5
}

// round 14
// speedup vs baseline: 3.1149x; 1.0150x over previous
#include <cuda_runtime.h>
#include <cuda_fp16.h>
#include <cstdint>

#define NB   4
#define SEQ  2048
#define DM   1024
#define MTOT (NB*SEQ)          // 8192
#define NW   (DM*DM)

#define BM 128
#define BN 128
#define BK 64
#define STAGES 3
#define TILE_BYTES (BM*BK*2)                // 16384 B per operand tile (128B rows)
#define SMEM_BYTES (STAGES*2*TILE_BYTES)    // 98304 B -> 2 CTAs/SM (192KB/228KB)

// ------------------------- scratch (__device__ globals; no allocs) ----------
__device__ __half g_X16[MTOT*DM];
__device__ __half g_Wq16[NW];
__device__ __half g_Wk16[NW];
__device__ __half g_Wv16[NW];
__device__ __half g_Q16[MTOT*DM];
__device__ __half g_K16[MTOT*DM];
__device__ __half g_V16[DM*MTOT];            // Vt: [DM, MTOT]
__device__ float  g_S[(size_t)MTOT*SEQ];
__device__ __half g_P16[(size_t)MTOT*SEQ];

// ------------------------- PTX helpers -------------------------------------
__device__ __forceinline__ void cp16(void* s, const void* g) {
    uint32_t sa = (uint32_t)__cvta_generic_to_shared(s);
    asm volatile("cp.async.cg.shared.global [%0], [%1], 16;\n" :: "r"(sa), "l"(g));
}
__device__ __forceinline__ void ldsm4(uint32_t* r, const void* p) {
    uint32_t a = (uint32_t)__cvta_generic_to_shared(p);
    asm volatile("ldmatrix.sync.aligned.m8n8.x4.shared.b16 {%0,%1,%2,%3}, [%4];\n"
                 : "=r"(r[0]), "=r"(r[1]), "=r"(r[2]), "=r"(r[3]) : "r"(a));
}
__device__ __forceinline__ void mma_f16(float* c, const uint32_t* a, const uint32_t* b) {
    asm volatile("mma.sync.aligned.m16n8k16.row.col.f32.f16.f16.f32 "
                 "{%0,%1,%2,%3}, {%4,%5,%6,%7}, {%8,%9}, {%0,%1,%2,%3};\n"
                 : "+f"(c[0]), "+f"(c[1]), "+f"(c[2]), "+f"(c[3])
                 : "r"(a[0]), "r"(a[1]), "r"(a[2]), "r"(a[3]), "r"(b[0]), "r"(b[1]));
}
// 128B rows, 8x16B chunks; chunk' = ch ^ (row&7).
__device__ __forceinline__ int smem_off(int row, int ch) {
    return (row << 7) + (((ch ^ (row & 7)) & 7) << 4);
}

// ------------------------- fp16 single-pass GEMM core -----------------------
// D[m][n] = scale * sum_k A[m][k]*B[n][k]  (both K-major fp16)
// OUT 0: fp16 output    OUT 1: fp32 * scale
template<int OUT>
__device__ __forceinline__ void gemm_core(
    const __half* __restrict__ A, int lda,
    const __half* __restrict__ B, int ldb,
    float* __restrict__ Cf, __half* __restrict__ C16, int ldc,
    int tm, int tn, int kIters, float scale, char* smem)
{
    char* sA = smem;
    char* sB = smem + STAGES * TILE_BYTES;

    const int tid  = threadIdx.x;
    const int lane = tid & 31;
    const int warp = tid >> 5;
    const int wm   = warp >> 2;   // 0..1 (64 rows each)
    const int wn   = warp & 3;    // 0..3 (32 cols each)

    auto load_stage = [&](int st, int kOff) {
        char* dA = sA + st * TILE_BYTES;
        char* dB = sB + st * TILE_BYTES;
#pragma unroll
        for (int i = 0; i < 4; i++) {
            int idx = tid + (i << 8);
            int row = idx >> 3, ch = idx & 7;
            int so = smem_off(row, ch);
            cp16(dA + so, A + (size_t)(tm + row) * lda + kOff + (ch << 3));
            cp16(dB + so, B + (size_t)(tn + row) * ldb + kOff + (ch << 3));
        }
    };

    // prologue: prefetch depth 2
#pragma unroll
    for (int s = 0; s < STAGES - 1; s++) {
        if (s < kIters) load_stage(s, s * BK);
        asm volatile("cp.async.commit_group;\n" ::);
    }

    float acc[4][4][4];
#pragma unroll
    for (int a = 0; a < 4; a++)
#pragma unroll
        for (int b = 0; b < 4; b++)
#pragma unroll
            for (int c = 0; c < 4; c++) acc[a][b][c] = 0.f;

    for (int kb = 0; kb < kIters; kb++) {
        asm volatile("cp.async.wait_group 1;\n" ::);   // stage kb resident
        __syncthreads();                                // single sync per iter
        int nk = kb + STAGES - 1;
        if (nk < kIters) load_stage(nk % STAGES, nk * BK);
        asm volatile("cp.async.commit_group;\n" ::);

        int st = kb % STAGES;
        const char* cA = sA + st * TILE_BYTES;
        const char* cB = sB + st * TILE_BYTES;

#pragma unroll
        for (int ks = 0; ks < 4; ks++) {
            // batch all 6 LDSMs up front (full MLP), then 16 uninterrupted HMMAs
            uint32_t ah[4][4], bh[2][4];
#pragma unroll
            for (int mi = 0; mi < 4; mi++) {
                int r  = wm * 64 + mi * 16 + (lane & 15);
                int ch = ks * 2 + (lane >> 4);
                ldsm4(ah[mi], cA + smem_off(r, ch));
            }
#pragma unroll
            for (int pr = 0; pr < 2; pr++) {
                int r  = wn * 32 + pr * 16 + (lane & 7) + (((lane >> 4) & 1) << 3);
                int ch = ks * 2 + ((lane >> 3) & 1);
                ldsm4(bh[pr], cB + smem_off(r, ch));
            }
#pragma unroll
            for (int pr = 0; pr < 2; pr++) {
                const int n0i = pr * 2;
#pragma unroll
                for (int mi = 0; mi < 4; mi++) {
                    mma_f16(acc[mi][n0i + 0], ah[mi], bh[pr] + 0);
                    mma_f16(acc[mi][n0i + 1], ah[mi], bh[pr] + 2);
                }
            }
        }
    }

    __syncthreads();

    const int g  = lane >> 2;
    const int tq = lane & 3;
#pragma unroll
    for (int mi = 0; mi < 4; mi++) {
#pragma unroll
        for (int ni = 0; ni < 4; ni++) {
            const float* c = acc[mi][ni];
            int c0 = tn + wn * 32 + ni * 8 + tq * 2;
#pragma unroll
            for (int h = 0; h < 2; h++) {
                int r = tm + wm * 64 + mi * 16 + g + h * 8;
                if (OUT == 0) {
                    __half2 hv;
                    hv.x = __float2half_rn(c[h * 2 + 0]);
                    hv.y = __float2half_rn(c[h * 2 + 1]);
                    *(__half2*)&C16[(size_t)r * ldc + c0] = hv;
                } else {
                    float2 o;
                    o.x = c[h * 2 + 0] * scale;
                    o.y = c[h * 2 + 1] * scale;
                    *(float2*)&Cf[(size_t)r * ldc + c0] = o;
                }
            }
        }
    }
}

// ------------------------- GEMM kernels -------------------------------------
// Merged projections: z=0 Q, z=1 K, z=2 Vt (role-swapped tiles)
__global__ void __launch_bounds__(256, 2) proj_k()
{
    extern __shared__ char smem[];
    int z = blockIdx.z;
    if (z == 0) {
        gemm_core<0>(g_X16, DM, g_Wq16, DM, nullptr, g_Q16, DM,
                     blockIdx.y * BM, blockIdx.x * BN, DM / BK, 1.f, smem);
    } else if (z == 1) {
        gemm_core<0>(g_X16, DM, g_Wk16, DM, nullptr, g_K16, DM,
                     blockIdx.y * BM, blockIdx.x * BN, DM / BK, 1.f, smem);
    } else {
        // Vt = Wv @ X^T -> [1024, 8192]; tm over DM (bx<8), tn over MTOT (by<64)
        gemm_core<0>(g_Wv16, DM, g_X16, DM, nullptr, g_V16, MTOT,
                     blockIdx.x * BM, blockIdx.y * BN, DM / BK, 1.f, smem);
    }
}

// Causal lower-triangle score tiles: S = (Q K^T)/32
__global__ void __launch_bounds__(256, 2) score_k()
{
    extern __shared__ char smem[];
    int b = blockIdx.z;
    int t = blockIdx.x, ib = 0;
    while ((ib + 1) * (ib + 2) / 2 <= t) ib++;
    int jb = t - ib * (ib + 1) / 2;
    size_t qo = (size_t)b * SEQ * DM;
    gemm_core<1>(g_Q16 + qo, DM, g_K16 + qo, DM,
                 g_S + (size_t)b * SEQ * SEQ, nullptr, SEQ,
                 ib * BM, jb * BN, DM / BK, 0.03125f, smem);
}

// O = P @ V, per-m-tile K limit. Largest-K tiles scheduled FIRST (reverse y)
// so the 32-iter CTAs start at t=0 and short ones backfill the tail.
__global__ void __launch_bounds__(256, 2) pv_k(float* __restrict__ out)
{
    extern __shared__ char smem[];
    int b = blockIdx.z;
    int my = (int)gridDim.y - 1 - (int)blockIdx.y;   // big tiles first
    gemm_core<1>(g_P16 + (size_t)b * SEQ * SEQ, SEQ,
                 g_V16 + (size_t)b * SEQ, MTOT,
                 out + (size_t)b * SEQ * DM, nullptr, DM,
                 my * BM, blockIdx.x * BN,
                 (my + 1) * BM / BK, 1.f, smem);
}

// ------------------------- converts -----------------------------------------
// fp32 -> fp16 (4 elems)
__device__ __forceinline__ void conv4h(const float* in, __half* out, int i) {
    float4 v = *(const float4*)(in + i);
    __half2 a; a.x = __float2half_rn(v.x); a.y = __float2half_rn(v.y);
    __half2 b; b.x = __float2half_rn(v.z); b.y = __float2half_rn(v.w);
    *(__half2*)(out + i)     = a;
    *(__half2*)(out + i + 2) = b;
}
__global__ void convX_k(const float* __restrict__ x) {
    int i = (blockIdx.x * 256 + threadIdx.x) * 4;
    if (i < MTOT * DM) conv4h(x, g_X16, i);
}
__global__ void convW_k(const float* __restrict__ wq,
                        const float* __restrict__ wk,
                        const float* __restrict__ wv) {
    int i = (blockIdx.x * 256 + threadIdx.x) * 4;
    if (i < NW)          conv4h(wq, g_Wq16, i);
    else if (i < 2 * NW) conv4h(wk + (i - NW),     g_Wk16 + (i - NW),     0);
    else if (i < 3 * NW) conv4h(wv + (i - 2 * NW), g_Wv16 + (i - 2 * NW), 0);
}

// ------------------------- causal row softmax -> P fp16 ---------------------
__global__ void __launch_bounds__(256) softmax_k(const float* __restrict__ S,
                                                 __half* __restrict__ P16)
{
    __shared__ float buf[SEQ];
    __shared__ float red[8];
    int row = blockIdx.x;
    int b = row >> 11, i = row & 2047;
    int L = i + 1;
    size_t off = ((size_t)b << 22) + ((size_t)i << 11);
    const float* s = S + off;
    int t = threadIdx.x;

    float m = -3.4e38f;
    for (int j = t; j < L; j += 256) { float v = s[j]; buf[j] = v; m = fmaxf(m, v); }
#pragma unroll
    for (int o = 16; o; o >>= 1) m = fmaxf(m, __shfl_xor_sync(0xffffffffu, m, o));
    if ((t & 31) == 0) red[t >> 5] = m;
    __syncthreads();
    float bm = fmaxf(fmaxf(fmaxf(red[0], red[1]), fmaxf(red[2], red[3])),
                     fmaxf(fmaxf(red[4], red[5]), fmaxf(red[6], red[7])));

    float sum = 0.f;
    for (int j = t; j < L; j += 256) { float p = __expf(buf[j] - bm); buf[j] = p; sum += p; }
#pragma unroll
    for (int o = 16; o; o >>= 1) sum += __shfl_xor_sync(0xffffffffu, sum, o);
    __syncthreads();
    if ((t & 31) == 0) red[t >> 5] = sum;
    __syncthreads();
    float tot = red[0] + red[1] + red[2] + red[3] + red[4] + red[5] + red[6] + red[7];
    float inv = 1.f / tot;

    int Lpad = (L + 127) & ~127;   // zero-fill to tile boundary for PV K-limit
    for (int j = t; j < Lpad; j += 256) {
        float v = (j < L) ? buf[j] * inv : 0.f;
        P16[off + j] = __float2half_rn(v);
    }
}

// ------------------------- host orchestration -------------------------------
extern "C" void kernel_launch(void* const* d_in, const int* in_sizes, int n_in,
                              void* d_out, int out_size)
{
    const float* x  = (const float*)d_in[0];
    const float* Wq = (const float*)d_in[1];
    const float* Wk = (const float*)d_in[2];
    const float* Wv = (const float*)d_in[3];
    float* out = (float*)d_out;

    __half* P16;  float* Sb;
    cudaGetSymbolAddress((void**)&P16, g_P16);
    cudaGetSymbolAddress((void**)&Sb,  g_S);

    cudaFuncSetAttribute(proj_k,  cudaFuncAttributeMaxDynamicSharedMemorySize, SMEM_BYTES);
    cudaFuncSetAttribute(score_k, cudaFuncAttributeMaxDynamicSharedMemorySize, SMEM_BYTES);
    cudaFuncSetAttribute(pv_k,    cudaFuncAttributeMaxDynamicSharedMemorySize, SMEM_BYTES);

    dim3 blk(256);
    convX_k<<<MTOT * DM / 4 / 256, 256>>>(x);                        // launch 0
    convW_k<<<3 * NW / 4 / 256, 256>>>(Wq, Wk, Wv);                  // launch 1
    proj_k<<<dim3(8, 64, 3), blk, SMEM_BYTES>>>();                   // launch 2
    score_k<<<dim3(136, 1, NB), blk, SMEM_BYTES>>>();                // launch 3
    softmax_k<<<MTOT, 256>>>(Sb, P16);                               // launch 4
    pv_k<<<dim3(DM / BN, SEQ / BM, NB), blk, SMEM_BYTES>>>(out);     // launch 5
}